// round 13
// baseline (speedup 1.0000x reference)
#include <cuda_runtime.h>
#include <cuda_fp16.h>
#include <math.h>
#include <stdint.h>

// Problem constants
#define BB 2
#define LL 2048
#define D_MODEL 768
#define D_INNER 1536
#define DT_RANK 16
#define D_STATE 16
#define D_CONV 4
#define MROWS (BB*LL)          // 4096
#define N_IN (2*D_INNER)       // 3072
#define N_DBL (DT_RANK + 2*D_STATE) // 48

// Scratch (static __device__ — no allocation in kernel_launch)
__device__ float  g_xz[(size_t)MROWS * N_IN];        // [4096,3072] fp32
__device__ float  g_xconv[(size_t)MROWS * D_INNER];  // [4096,1536]
__device__ float  g_xdbl[(size_t)MROWS * N_DBL];     // [4096,48]
__device__ float  g_dt[(size_t)MROWS * D_INNER];     // [4096,1536]
__device__ __half g_xh[(size_t)MROWS * D_MODEL];     // x in half
__device__ __half g_w1th[(size_t)N_IN * D_MODEL];    // W_in^T  [3072,768] half
__device__ __half g_w2th[(size_t)D_MODEL * D_INNER]; // W_out^T [768,1536] half
__device__ __half g_ygh[(size_t)MROWS * D_INNER];    // gated y in half

// ---------------------------------------------------------------------------
// FP16 tensor-core GEMM (mma.m16n8k16, fp32 accum), 3-stage cp.async pipeline.
// C[M,N] = A[M,K] * Bt[N,K]^T, A/Bt half K-major, C fp32.
// CTA tile 128x128, 4 warps (2x2), warp tile 64x64, BK = 64 halves (128B rows,
// SW128 XOR swizzle -> conflict-free cp.async stores AND fragment LDS).
// Requires M%128==0, N%128==0, K%64==0.
// ---------------------------------------------------------------------------
__device__ __forceinline__ uint32_t smem_u32(const void* p) {
    return (uint32_t)__cvta_generic_to_shared(p);
}
#define CP_ASYNC16(dst, src) \
    asm volatile("cp.async.cg.shared.global [%0], [%1], 16;" :: "r"(dst), "l"(src))
#define CP_COMMIT() asm volatile("cp.async.commit_group;")
#define CP_WAIT2()  asm volatile("cp.async.wait_group 2;")

#define MMA_F16(d, a, b) \
    asm volatile("mma.sync.aligned.m16n8k16.row.col.f32.f16.f16.f32 " \
                 "{%0,%1,%2,%3},{%4,%5,%6,%7},{%8,%9},{%0,%1,%2,%3};" \
                 : "+f"((d)[0]), "+f"((d)[1]), "+f"((d)[2]), "+f"((d)[3]) \
                 : "r"((a)[0]), "r"((a)[1]), "r"((a)[2]), "r"((a)[3]), \
                   "r"((b)[0]), "r"((b)[1]))

// swizzled byte offset within a 128x64-half tile (128B per row)
__device__ __forceinline__ uint32_t sw_off(int r, int col) {
    return ((uint32_t)r << 7) + ((uint32_t)(((col >> 3) ^ (r & 7))) << 4)
         + ((uint32_t)(col & 7) << 1);
}

#define GSTAGES 3
#define TILE_BYTES 16384            // 128 rows * 128 B
#define STAGE_BYTES (2 * TILE_BYTES)

__global__ __launch_bounds__(128) void h16_gemm(
    const __half* __restrict__ A, const __half* __restrict__ Bt,
    float* __restrict__ C, int M, int N, int K)
{
    extern __shared__ __align__(1024) char sm[];

    const int tid  = threadIdx.x;
    const int lane = tid & 31;
    const int warp = tid >> 5;          // 0..3
    const int wm   = warp >> 1;         // 0..1 (64 rows)
    const int wn   = warp & 1;          // 0..1 (64 cols)
    const int bx = blockIdx.x, by = blockIdx.y;
    const int m0 = by * 128, n0 = bx * 128;
    const int KT = K >> 6;              // k-tiles of 64 halves

    // stage pointers
    char* smA[GSTAGES];
    char* smB[GSTAGES];
    #pragma unroll
    for (int s = 0; s < GSTAGES; s++) {
        smA[s] = sm + s * STAGE_BYTES;
        smB[s] = sm + s * STAGE_BYTES + TILE_BYTES;
    }

    // loader: 128x64 halves = 1024 x 16B chunks per matrix; 8 chunks/thread each
#define LOAD_STAGE(s, kt) do { \
        const __half* Agp = A + (size_t)m0 * K + (size_t)(kt) * 64; \
        const __half* Bgp = Bt + (size_t)n0 * K + (size_t)(kt) * 64; \
        _Pragma("unroll") \
        for (int i = 0; i < 8; i++) { \
            int e = tid + (i << 7); \
            int r = e >> 3, c = e & 7; \
            uint32_t off = ((uint32_t)r << 7) + ((uint32_t)((c ^ (r & 7))) << 4); \
            CP_ASYNC16(smem_u32(smA[s] + off), Agp + (size_t)r * K + (c << 3)); \
            CP_ASYNC16(smem_u32(smB[s] + off), Bgp + (size_t)r * K + (c << 3)); \
        } \
    } while (0)

    LOAD_STAGE(0, 0); CP_COMMIT();
    if (KT > 1) LOAD_STAGE(1, 1);
    CP_COMMIT();

    float acc[4][8][4];
    #pragma unroll
    for (int mt = 0; mt < 4; mt++)
        #pragma unroll
        for (int nt = 0; nt < 8; nt++)
            #pragma unroll
            for (int i = 0; i < 4; i++) acc[mt][nt][i] = 0.f;

    for (int kt = 0; kt < KT; kt++) {
        // stage kt+2 (buffer freed by compute kt-1, retired by trailing sync)
        if (kt + 2 < KT) LOAD_STAGE((kt + 2) % GSTAGES, kt + 2);
        CP_COMMIT();
        CP_WAIT2();              // groups 1..kt+1 done -> stage kt ready
        __syncthreads();

        const char* Ab = smA[kt % GSTAGES];
        const char* Bb = smB[kt % GSTAGES];
        const int q2 = 2 * (lane & 3);

        #pragma unroll
        for (int ks = 0; ks < 4; ks++) {
            const int colL = ks * 16 + q2;
            const int colH = colL + 8;
            uint32_t af[4][4];
            #pragma unroll
            for (int mt = 0; mt < 4; mt++) {
                int r1 = wm * 64 + mt * 16 + (lane >> 2);
                af[mt][0] = *(const uint32_t*)(Ab + sw_off(r1,     colL));
                af[mt][1] = *(const uint32_t*)(Ab + sw_off(r1 + 8, colL));
                af[mt][2] = *(const uint32_t*)(Ab + sw_off(r1,     colH));
                af[mt][3] = *(const uint32_t*)(Ab + sw_off(r1 + 8, colH));
            }
            uint32_t bf[8][2];
            #pragma unroll
            for (int nt = 0; nt < 8; nt++) {
                int n1 = wn * 64 + nt * 8 + (lane >> 2);
                bf[nt][0] = *(const uint32_t*)(Bb + sw_off(n1, colL));
                bf[nt][1] = *(const uint32_t*)(Bb + sw_off(n1, colH));
            }
            #pragma unroll
            for (int mt = 0; mt < 4; mt++)
                #pragma unroll
                for (int nt = 0; nt < 8; nt++)
                    MMA_F16(acc[mt][nt], af[mt], bf[nt]);
        }
        __syncthreads();
    }
#undef LOAD_STAGE

    // epilogue: write C fp32
    #pragma unroll
    for (int mt = 0; mt < 4; mt++) {
        #pragma unroll
        for (int nt = 0; nt < 8; nt++) {
            int row = m0 + wm * 64 + mt * 16 + (lane >> 2);
            int col = n0 + wn * 64 + nt * 8 + 2 * (lane & 3);
            float2 v0 = make_float2(acc[mt][nt][0], acc[mt][nt][1]);
            float2 v1 = make_float2(acc[mt][nt][2], acc[mt][nt][3]);
            *(float2*)(C + (size_t)row * N + col)       = v0;
            *(float2*)(C + (size_t)(row + 8) * N + col) = v1;
        }
    }
}

// ---------------------------------------------------------------------------
// fp32 -> fp16 convert (vectorized).
// ---------------------------------------------------------------------------
__global__ void f2h_kernel(const float* __restrict__ in, __half* __restrict__ out, int n)
{
    int i = (blockIdx.x * blockDim.x + threadIdx.x) * 4;
    if (i >= n) return;
    float4 v = *(const float4*)(in + i);
    __half2 h0 = __floats2half2_rn(v.x, v.y);
    __half2 h1 = __floats2half2_rn(v.z, v.w);
    *(uint2*)(out + i) = make_uint2(*(uint32_t*)&h0, *(uint32_t*)&h1);
}

// ---------------------------------------------------------------------------
// 32x32 tiled transpose + convert: out_h[c][r] = (half)in[r][c].
// ---------------------------------------------------------------------------
__global__ void transpose_h_kernel(const float* __restrict__ in, __half* __restrict__ out,
                                   int R, int C)
{
    __shared__ float t[32][33];
    int cb = blockIdx.x * 32, rb = blockIdx.y * 32;
    int x = threadIdx.x, y = threadIdx.y;   // block (32, 8)
    #pragma unroll
    for (int i = 0; i < 32; i += 8)
        t[y + i][x] = in[(size_t)(rb + y + i) * C + cb + x];
    __syncthreads();
    #pragma unroll
    for (int i = 0; i < 32; i += 8)
        out[(size_t)(cb + y + i) * R + rb + x] = __float2half(t[x][y + i]);
}

// ---------------------------------------------------------------------------
// Causal depthwise conv1d (width 4) + silu.
// ---------------------------------------------------------------------------
__global__ void conv_silu_kernel(const float* __restrict__ conv_w,
                                 const float* __restrict__ conv_b)
{
    int idx = blockIdx.x * blockDim.x + threadIdx.x;   // over 4096*1536
    if (idx >= MROWS * D_INNER) return;
    int d = idx % D_INNER;
    int r = idx / D_INNER;
    int l = r % LL;

    float w0 = conv_w[d*4+0], w1 = conv_w[d*4+1], w2 = conv_w[d*4+2], w3 = conv_w[d*4+3];
    const float* base = g_xz + (size_t)r * N_IN + d;

    float acc = conv_b[d] + w3 * base[0];
    if (l >= 1) acc += w2 * base[-(size_t)N_IN];
    if (l >= 2) acc += w1 * base[-2*(size_t)N_IN];
    if (l >= 3) acc += w0 * base[-3*(size_t)N_IN];
    g_xconv[idx] = acc / (1.f + __expf(-acc));   // silu
}

// ---------------------------------------------------------------------------
// x_dbl = x_conv @ W_x  ([4096,1536] x [1536,48]).
// ---------------------------------------------------------------------------
__global__ __launch_bounds__(256) void xdbl_kernel(const float* __restrict__ Wx)
{
    const int tx = threadIdx.x & 15;
    const int ty = threadIdx.x >> 4;
    const int r0 = blockIdx.x * 64;

    float acc[4][3] = {};
    #pragma unroll 4
    for (int k = 0; k < D_INNER; k++) {
        float w0 = Wx[k * N_DBL + tx];
        float w1 = Wx[k * N_DBL + tx + 16];
        float w2 = Wx[k * N_DBL + tx + 32];
        #pragma unroll
        for (int rr = 0; rr < 4; rr++) {
            float xv = g_xconv[(size_t)(r0 + ty + rr * 16) * D_INNER + k];
            acc[rr][0] += xv * w0;
            acc[rr][1] += xv * w1;
            acc[rr][2] += xv * w2;
        }
    }
    #pragma unroll
    for (int rr = 0; rr < 4; rr++) {
        int r = r0 + ty + rr * 16;
        g_xdbl[(size_t)r * N_DBL + tx]      = acc[rr][0];
        g_xdbl[(size_t)r * N_DBL + tx + 16] = acc[rr][1];
        g_xdbl[(size_t)r * N_DBL + tx + 32] = acc[rr][2];
    }
}

// ---------------------------------------------------------------------------
// dt = softplus(dt_low @ W_dt + b_dt)    K=16, thread per output.
// ---------------------------------------------------------------------------
__global__ void dt_kernel(const float* __restrict__ Wdt, const float* __restrict__ bdt)
{
    int idx = blockIdx.x * blockDim.x + threadIdx.x;
    if (idx >= MROWS * D_INNER) return;
    int d = idx % D_INNER;
    int r = idx / D_INNER;
    float acc = bdt[d];
    #pragma unroll
    for (int k = 0; k < DT_RANK; k++)
        acc += g_xdbl[(size_t)r * N_DBL + k] * Wdt[(size_t)k * D_INNER + d];
    g_dt[idx] = (acc > 20.f) ? acc : log1pf(__expf(acc));
}

// ---------------------------------------------------------------------------
// Selective scan with deep software pipeline; epilogue writes half for gemm2.
// ---------------------------------------------------------------------------
#define UF 8

__global__ __launch_bounds__(64) void scan_kernel(
    const float* __restrict__ A_log, const float* __restrict__ Dvec)
{
    const int n  = threadIdx.x & 15;
    const int ch = blockIdx.x * 4 + (threadIdx.x >> 4);  // 0..3071
    const int b  = ch / D_INNER;
    const int d  = ch % D_INNER;

    const float A  = -__expf(A_log[d * D_STATE + n]);
    const float Dd = Dvec[d];

    const float* xc  = g_xconv + (size_t)b * LL * D_INNER + d;
    const float* dtp = g_dt    + (size_t)b * LL * D_INNER + d;
    const float* bc  = g_xdbl  + (size_t)b * LL * N_DBL;
    const float* zp  = g_xz    + (size_t)b * LL * N_IN + D_INNER + d;
    __half*      yp  = g_ygh   + (size_t)b * LL * D_INNER + d;

    float h = 0.f;

    float uA[UF], dA_[UF], BA[UF], CA[UF], zA[UF];
    float uB[UF], dB_[UF], BBf[UF], CB[UF], zB[UF];

    auto loadblk = [&](int t0, float* U, float* DT, float* Bv, float* Cv, float* Z) {
        #pragma unroll
        for (int i = 0; i < UF; i++) {
            size_t t = (size_t)(t0 + i);
            U[i]  = __ldg(xc  + t * D_INNER);
            DT[i] = __ldg(dtp + t * D_INNER);
            Bv[i] = __ldg(bc  + t * N_DBL + DT_RANK + n);
            Cv[i] = __ldg(bc  + t * N_DBL + DT_RANK + D_STATE + n);
            Z[i]  = __ldg(zp  + t * N_IN);
        }
    };
    auto compute = [&](int t0, const float* U, const float* DT,
                       const float* Bv, const float* Cv, const float* Z) {
        #pragma unroll
        for (int i = 0; i < UF; i++) {
            float dA = __expf(A * DT[i]);
            h = h * dA + (DT[i] * U[i]) * Bv[i];

            float p = Cv[i] * h;
            p += __shfl_xor_sync(0xffffffffu, p, 8);
            p += __shfl_xor_sync(0xffffffffu, p, 4);
            p += __shfl_xor_sync(0xffffffffu, p, 2);
            p += __shfl_xor_sync(0xffffffffu, p, 1);

            if (n == 0) {
                float zv = Z[i];
                float zs = zv / (1.f + __expf(-zv));
                yp[(size_t)(t0 + i) * D_INNER] = __float2half((p + U[i] * Dd) * zs);
            }
        }
    };

    loadblk(0, uA, dA_, BA, CA, zA);

    for (int t0 = 0; t0 < LL; t0 += 2 * UF) {
        loadblk(t0 + UF, uB, dB_, BBf, CB, zB);
        compute(t0, uA, dA_, BA, CA, zA);
        if (t0 + 2 * UF < LL)
            loadblk(t0 + 2 * UF, uA, dA_, BA, CA, zA);
        compute(t0 + UF, uB, dB_, BBf, CB, zB);
    }
}

// ---------------------------------------------------------------------------
extern "C" void kernel_launch(void* const* d_in, const int* in_sizes, int n_in,
                              void* d_out, int out_size)
{
    const float* x      = (const float*)d_in[0];
    const float* W_in   = (const float*)d_in[1];
    const float* conv_w = (const float*)d_in[2];
    const float* conv_b = (const float*)d_in[3];
    const float* W_x    = (const float*)d_in[4];
    const float* W_dt   = (const float*)d_in[5];
    const float* b_dt   = (const float*)d_in[6];
    const float* A_log  = (const float*)d_in[7];
    const float* Dvec   = (const float*)d_in[8];
    const float* W_out  = (const float*)d_in[9];
    float* out = (float*)d_out;

    float *xz_p;
    __half *xh_p, *w1th_p, *w2th_p, *ygh_p;
    cudaGetSymbolAddress((void**)&xz_p,   g_xz);
    cudaGetSymbolAddress((void**)&xh_p,   g_xh);
    cudaGetSymbolAddress((void**)&w1th_p, g_w1th);
    cudaGetSymbolAddress((void**)&w2th_p, g_w2th);
    cudaGetSymbolAddress((void**)&ygh_p,  g_ygh);

    static bool attr_set = false;
    if (!attr_set) {
        cudaFuncSetAttribute(h16_gemm, cudaFuncAttributeMaxDynamicSharedMemorySize,
                             GSTAGES * STAGE_BYTES);
        attr_set = true;
    }

    // 1) x -> half
    {
        int n = MROWS * D_MODEL;
        f2h_kernel<<<(n / 4 + 255) / 256, 256>>>(x, xh_p, n);
    }
    // 2-3) weights -> half K-major (transposed)
    {
        dim3 blk(32, 8);
        transpose_h_kernel<<<dim3(N_IN / 32, D_MODEL / 32), blk>>>(W_in, w1th_p, D_MODEL, N_IN);
        transpose_h_kernel<<<dim3(D_MODEL / 32, D_INNER / 32), blk>>>(W_out, w2th_p, D_INNER, D_MODEL);
    }
    // 4) xz = x @ W_in   [4096,768] x [768,3072]  (fp16 HMMA)
    {
        dim3 grid(N_IN / 128, MROWS / 128);
        h16_gemm<<<grid, 128, GSTAGES * STAGE_BYTES>>>(xh_p, w1th_p, xz_p, MROWS, N_IN, D_MODEL);
    }
    // 5) causal conv + silu
    {
        int total = MROWS * D_INNER;
        conv_silu_kernel<<<(total + 255) / 256, 256>>>(conv_w, conv_b);
    }
    // 6) x_dbl = x_conv @ W_x
    xdbl_kernel<<<MROWS / 64, 256>>>(W_x);
    // 7) dt = softplus(dt_low @ W_dt + b_dt)
    {
        int total = MROWS * D_INNER;
        dt_kernel<<<(total + 255) / 256, 256>>>(W_dt, b_dt);
    }
    // 8) selective scan + gate (writes half)
    scan_kernel<<<(BB * D_INNER) / 4, 64>>>(A_log, Dvec);
    // 9) out = y_gated @ W_out   [4096,1536] x [1536,768]  (fp16 HMMA)
    {
        dim3 grid(D_MODEL / 128, MROWS / 128);
        h16_gemm<<<grid, 128, GSTAGES * STAGE_BYTES>>>(ygh_p, w2th_p, out, MROWS, D_MODEL, D_INNER);
    }
}

// round 14
// speedup vs baseline: 1.4074x; 1.4074x over previous
#include <cuda_runtime.h>
#include <cuda_fp16.h>
#include <math.h>
#include <stdint.h>

// Problem constants
#define BB 2
#define LL 2048
#define D_MODEL 768
#define D_INNER 1536
#define DT_RANK 16
#define D_STATE 16
#define D_CONV 4
#define MROWS (BB*LL)          // 4096
#define N_IN (2*D_INNER)       // 3072
#define N_DBL (DT_RANK + 2*D_STATE) // 48

// Scratch (static __device__ — no allocation in kernel_launch)
__device__ float  g_xz[(size_t)MROWS * N_IN];        // [4096,3072] fp32
__device__ float  g_xconv[(size_t)MROWS * D_INNER];  // [4096,1536]
__device__ float  g_xdbl[(size_t)MROWS * N_DBL];     // [4096,48]
__device__ float  g_dt[(size_t)MROWS * D_INNER];     // [4096,1536]
__device__ __half g_xh[(size_t)MROWS * D_MODEL];     // x in half
__device__ __half g_w1th[(size_t)N_IN * D_MODEL];    // W_in^T  [3072,768] half
__device__ __half g_w2th[(size_t)D_MODEL * D_INNER]; // W_out^T [768,1536] half
__device__ __half g_ygh[(size_t)MROWS * D_INNER];    // gated y in half

// ---------------------------------------------------------------------------
// FP16 tensor-core GEMM (mma.m16n8k16, fp32 accum), 3-stage cp.async pipeline.
// C[M,N] = A[M,K] * Bt[N,K]^T, A/Bt half K-major, C fp32.
// CTA tile 128x128, 8 warps (4m x 2n), warp tile 32x64, BK = 64 halves
// (128B rows, SW128 XOR swizzle -> conflict-free cp.async + fragment LDS).
// Requires M%128==0, N%128==0, K%64==0.
// ---------------------------------------------------------------------------
__device__ __forceinline__ uint32_t smem_u32(const void* p) {
    return (uint32_t)__cvta_generic_to_shared(p);
}
#define CP_ASYNC16(dst, src) \
    asm volatile("cp.async.cg.shared.global [%0], [%1], 16;" :: "r"(dst), "l"(src))
#define CP_COMMIT() asm volatile("cp.async.commit_group;")
#define CP_WAIT2()  asm volatile("cp.async.wait_group 2;")

#define MMA_F16(d, a, b) \
    asm volatile("mma.sync.aligned.m16n8k16.row.col.f32.f16.f16.f32 " \
                 "{%0,%1,%2,%3},{%4,%5,%6,%7},{%8,%9},{%0,%1,%2,%3};" \
                 : "+f"((d)[0]), "+f"((d)[1]), "+f"((d)[2]), "+f"((d)[3]) \
                 : "r"((a)[0]), "r"((a)[1]), "r"((a)[2]), "r"((a)[3]), \
                   "r"((b)[0]), "r"((b)[1]))

// swizzled byte offset within a 128x64-half tile (128B per row)
__device__ __forceinline__ uint32_t sw_off(int r, int col) {
    return ((uint32_t)r << 7) + ((uint32_t)(((col >> 3) ^ (r & 7))) << 4)
         + ((uint32_t)(col & 7) << 1);
}

#define GSTAGES 3
#define TILE_BYTES 16384            // 128 rows * 128 B
#define STAGE_BYTES (2 * TILE_BYTES)

__global__ __launch_bounds__(256) void h16_gemm(
    const __half* __restrict__ A, const __half* __restrict__ Bt,
    float* __restrict__ C, int M, int N, int K)
{
    extern __shared__ __align__(1024) char sm[];

    const int tid  = threadIdx.x;
    const int lane = tid & 31;
    const int warp = tid >> 5;          // 0..7
    const int wm   = warp >> 1;         // 0..3 (32 rows)
    const int wn   = warp & 1;          // 0..1 (64 cols)
    const int bx = blockIdx.x, by = blockIdx.y;
    const int m0 = by * 128, n0 = bx * 128;
    const int KT = K >> 6;              // k-tiles of 64 halves

    char* smA[GSTAGES];
    char* smB[GSTAGES];
    #pragma unroll
    for (int s = 0; s < GSTAGES; s++) {
        smA[s] = sm + s * STAGE_BYTES;
        smB[s] = sm + s * STAGE_BYTES + TILE_BYTES;
    }

    // loader: 128x64 halves = 1024 x 16B chunks per matrix; 4 chunks/thread each
#define LOAD_STAGE(s, kt) do { \
        const __half* Agp = A + (size_t)m0 * K + (size_t)(kt) * 64; \
        const __half* Bgp = Bt + (size_t)n0 * K + (size_t)(kt) * 64; \
        _Pragma("unroll") \
        for (int i = 0; i < 4; i++) { \
            int e = tid + (i << 8); \
            int r = e >> 3, c = e & 7; \
            uint32_t off = ((uint32_t)r << 7) + ((uint32_t)((c ^ (r & 7))) << 4); \
            CP_ASYNC16(smem_u32(smA[s] + off), Agp + (size_t)r * K + (c << 3)); \
            CP_ASYNC16(smem_u32(smB[s] + off), Bgp + (size_t)r * K + (c << 3)); \
        } \
    } while (0)

    LOAD_STAGE(0, 0); CP_COMMIT();
    if (KT > 1) LOAD_STAGE(1, 1);
    CP_COMMIT();

    float acc[2][8][4];
    #pragma unroll
    for (int mt = 0; mt < 2; mt++)
        #pragma unroll
        for (int nt = 0; nt < 8; nt++)
            #pragma unroll
            for (int i = 0; i < 4; i++) acc[mt][nt][i] = 0.f;

    for (int kt = 0; kt < KT; kt++) {
        if (kt + 2 < KT) LOAD_STAGE((kt + 2) % GSTAGES, kt + 2);
        CP_COMMIT();
        CP_WAIT2();              // stage kt ready
        __syncthreads();

        const char* Ab = smA[kt % GSTAGES];
        const char* Bb = smB[kt % GSTAGES];
        const int q2 = 2 * (lane & 3);

        #pragma unroll
        for (int ks = 0; ks < 4; ks++) {
            const int colL = ks * 16 + q2;
            const int colH = colL + 8;
            uint32_t af[2][4];
            #pragma unroll
            for (int mt = 0; mt < 2; mt++) {
                int r1 = wm * 32 + mt * 16 + (lane >> 2);
                af[mt][0] = *(const uint32_t*)(Ab + sw_off(r1,     colL));
                af[mt][1] = *(const uint32_t*)(Ab + sw_off(r1 + 8, colL));
                af[mt][2] = *(const uint32_t*)(Ab + sw_off(r1,     colH));
                af[mt][3] = *(const uint32_t*)(Ab + sw_off(r1 + 8, colH));
            }
            uint32_t bf[8][2];
            #pragma unroll
            for (int nt = 0; nt < 8; nt++) {
                int n1 = wn * 64 + nt * 8 + (lane >> 2);
                bf[nt][0] = *(const uint32_t*)(Bb + sw_off(n1, colL));
                bf[nt][1] = *(const uint32_t*)(Bb + sw_off(n1, colH));
            }
            #pragma unroll
            for (int mt = 0; mt < 2; mt++)
                #pragma unroll
                for (int nt = 0; nt < 8; nt++)
                    MMA_F16(acc[mt][nt], af[mt], bf[nt]);
        }
        __syncthreads();
    }
#undef LOAD_STAGE

    // epilogue: write C fp32
    #pragma unroll
    for (int mt = 0; mt < 2; mt++) {
        #pragma unroll
        for (int nt = 0; nt < 8; nt++) {
            int row = m0 + wm * 32 + mt * 16 + (lane >> 2);
            int col = n0 + wn * 64 + nt * 8 + 2 * (lane & 3);
            float2 v0 = make_float2(acc[mt][nt][0], acc[mt][nt][1]);
            float2 v1 = make_float2(acc[mt][nt][2], acc[mt][nt][3]);
            *(float2*)(C + (size_t)row * N + col)       = v0;
            *(float2*)(C + (size_t)(row + 8) * N + col) = v1;
        }
    }
}

// ---------------------------------------------------------------------------
// fp32 -> fp16 convert (vectorized).
// ---------------------------------------------------------------------------
__global__ void f2h_kernel(const float* __restrict__ in, __half* __restrict__ out, int n)
{
    int i = (blockIdx.x * blockDim.x + threadIdx.x) * 4;
    if (i >= n) return;
    float4 v = *(const float4*)(in + i);
    __half2 h0 = __floats2half2_rn(v.x, v.y);
    __half2 h1 = __floats2half2_rn(v.z, v.w);
    *(uint2*)(out + i) = make_uint2(*(uint32_t*)&h0, *(uint32_t*)&h1);
}

// ---------------------------------------------------------------------------
// 32x32 tiled transpose + convert: out_h[c][r] = (half)in[r][c].
// ---------------------------------------------------------------------------
__global__ void transpose_h_kernel(const float* __restrict__ in, __half* __restrict__ out,
                                   int R, int C)
{
    __shared__ float t[32][33];
    int cb = blockIdx.x * 32, rb = blockIdx.y * 32;
    int x = threadIdx.x, y = threadIdx.y;   // block (32, 8)
    #pragma unroll
    for (int i = 0; i < 32; i += 8)
        t[y + i][x] = in[(size_t)(rb + y + i) * C + cb + x];
    __syncthreads();
    #pragma unroll
    for (int i = 0; i < 32; i += 8)
        out[(size_t)(cb + y + i) * R + rb + x] = __float2half(t[x][y + i]);
}

// ---------------------------------------------------------------------------
// Causal depthwise conv1d (width 4) + silu.
// ---------------------------------------------------------------------------
__global__ void conv_silu_kernel(const float* __restrict__ conv_w,
                                 const float* __restrict__ conv_b)
{
    int idx = blockIdx.x * blockDim.x + threadIdx.x;   // over 4096*1536
    if (idx >= MROWS * D_INNER) return;
    int d = idx % D_INNER;
    int r = idx / D_INNER;
    int l = r % LL;

    float w0 = conv_w[d*4+0], w1 = conv_w[d*4+1], w2 = conv_w[d*4+2], w3 = conv_w[d*4+3];
    const float* base = g_xz + (size_t)r * N_IN + d;

    float acc = conv_b[d] + w3 * base[0];
    if (l >= 1) acc += w2 * base[-(size_t)N_IN];
    if (l >= 2) acc += w1 * base[-2*(size_t)N_IN];
    if (l >= 3) acc += w0 * base[-3*(size_t)N_IN];
    g_xconv[idx] = acc / (1.f + __expf(-acc));   // silu
}

// ---------------------------------------------------------------------------
// x_dbl = x_conv @ W_x  ([4096,1536] x [1536,48]).
// ---------------------------------------------------------------------------
__global__ __launch_bounds__(256) void xdbl_kernel(const float* __restrict__ Wx)
{
    const int tx = threadIdx.x & 15;
    const int ty = threadIdx.x >> 4;
    const int r0 = blockIdx.x * 64;

    float acc[4][3] = {};
    #pragma unroll 4
    for (int k = 0; k < D_INNER; k++) {
        float w0 = Wx[k * N_DBL + tx];
        float w1 = Wx[k * N_DBL + tx + 16];
        float w2 = Wx[k * N_DBL + tx + 32];
        #pragma unroll
        for (int rr = 0; rr < 4; rr++) {
            float xv = g_xconv[(size_t)(r0 + ty + rr * 16) * D_INNER + k];
            acc[rr][0] += xv * w0;
            acc[rr][1] += xv * w1;
            acc[rr][2] += xv * w2;
        }
    }
    #pragma unroll
    for (int rr = 0; rr < 4; rr++) {
        int r = r0 + ty + rr * 16;
        g_xdbl[(size_t)r * N_DBL + tx]      = acc[rr][0];
        g_xdbl[(size_t)r * N_DBL + tx + 16] = acc[rr][1];
        g_xdbl[(size_t)r * N_DBL + tx + 32] = acc[rr][2];
    }
}

// ---------------------------------------------------------------------------
// dt = softplus(dt_low @ W_dt + b_dt)    K=16, thread per output.
// ---------------------------------------------------------------------------
__global__ void dt_kernel(const float* __restrict__ Wdt, const float* __restrict__ bdt)
{
    int idx = blockIdx.x * blockDim.x + threadIdx.x;
    if (idx >= MROWS * D_INNER) return;
    int d = idx % D_INNER;
    int r = idx / D_INNER;
    float acc = bdt[d];
    #pragma unroll
    for (int k = 0; k < DT_RANK; k++)
        acc += g_xdbl[(size_t)r * N_DBL + k] * Wdt[(size_t)k * D_INNER + d];
    g_dt[idx] = (acc > 20.f) ? acc : log1pf(__expf(acc));
}

// ---------------------------------------------------------------------------
// Selective scan with deep software pipeline; epilogue writes half for gemm2.
// ---------------------------------------------------------------------------
#define UF 8

__global__ __launch_bounds__(64) void scan_kernel(
    const float* __restrict__ A_log, const float* __restrict__ Dvec)
{
    const int n  = threadIdx.x & 15;
    const int ch = blockIdx.x * 4 + (threadIdx.x >> 4);  // 0..3071
    const int b  = ch / D_INNER;
    const int d  = ch % D_INNER;

    const float A  = -__expf(A_log[d * D_STATE + n]);
    const float Dd = Dvec[d];

    const float* xc  = g_xconv + (size_t)b * LL * D_INNER + d;
    const float* dtp = g_dt    + (size_t)b * LL * D_INNER + d;
    const float* bc  = g_xdbl  + (size_t)b * LL * N_DBL;
    const float* zp  = g_xz    + (size_t)b * LL * N_IN + D_INNER + d;
    __half*      yp  = g_ygh   + (size_t)b * LL * D_INNER + d;

    float h = 0.f;

    float uA[UF], dA_[UF], BA[UF], CA[UF], zA[UF];
    float uB[UF], dB_[UF], BBf[UF], CB[UF], zB[UF];

    auto loadblk = [&](int t0, float* U, float* DT, float* Bv, float* Cv, float* Z) {
        #pragma unroll
        for (int i = 0; i < UF; i++) {
            size_t t = (size_t)(t0 + i);
            U[i]  = __ldg(xc  + t * D_INNER);
            DT[i] = __ldg(dtp + t * D_INNER);
            Bv[i] = __ldg(bc  + t * N_DBL + DT_RANK + n);
            Cv[i] = __ldg(bc  + t * N_DBL + DT_RANK + D_STATE + n);
            Z[i]  = __ldg(zp  + t * N_IN);
        }
    };
    auto compute = [&](int t0, const float* U, const float* DT,
                       const float* Bv, const float* Cv, const float* Z) {
        #pragma unroll
        for (int i = 0; i < UF; i++) {
            float dA = __expf(A * DT[i]);
            h = h * dA + (DT[i] * U[i]) * Bv[i];

            float p = Cv[i] * h;
            p += __shfl_xor_sync(0xffffffffu, p, 8);
            p += __shfl_xor_sync(0xffffffffu, p, 4);
            p += __shfl_xor_sync(0xffffffffu, p, 2);
            p += __shfl_xor_sync(0xffffffffu, p, 1);

            if (n == 0) {
                float zv = Z[i];
                float zs = zv / (1.f + __expf(-zv));
                yp[(size_t)(t0 + i) * D_INNER] = __float2half((p + U[i] * Dd) * zs);
            }
        }
    };

    loadblk(0, uA, dA_, BA, CA, zA);

    for (int t0 = 0; t0 < LL; t0 += 2 * UF) {
        loadblk(t0 + UF, uB, dB_, BBf, CB, zB);
        compute(t0, uA, dA_, BA, CA, zA);
        if (t0 + 2 * UF < LL)
            loadblk(t0 + 2 * UF, uA, dA_, BA, CA, zA);
        compute(t0 + UF, uB, dB_, BBf, CB, zB);
    }
}

// ---------------------------------------------------------------------------
extern "C" void kernel_launch(void* const* d_in, const int* in_sizes, int n_in,
                              void* d_out, int out_size)
{
    const float* x      = (const float*)d_in[0];
    const float* W_in   = (const float*)d_in[1];
    const float* conv_w = (const float*)d_in[2];
    const float* conv_b = (const float*)d_in[3];
    const float* W_x    = (const float*)d_in[4];
    const float* W_dt   = (const float*)d_in[5];
    const float* b_dt   = (const float*)d_in[6];
    const float* A_log  = (const float*)d_in[7];
    const float* Dvec   = (const float*)d_in[8];
    const float* W_out  = (const float*)d_in[9];
    float* out = (float*)d_out;

    float *xz_p;
    __half *xh_p, *w1th_p, *w2th_p, *ygh_p;
    cudaGetSymbolAddress((void**)&xz_p,   g_xz);
    cudaGetSymbolAddress((void**)&xh_p,   g_xh);
    cudaGetSymbolAddress((void**)&w1th_p, g_w1th);
    cudaGetSymbolAddress((void**)&w2th_p, g_w2th);
    cudaGetSymbolAddress((void**)&ygh_p,  g_ygh);

    cudaFuncSetAttribute(h16_gemm, cudaFuncAttributeMaxDynamicSharedMemorySize,
                         GSTAGES * STAGE_BYTES);

    // 1) x -> half
    {
        int n = MROWS * D_MODEL;
        f2h_kernel<<<(n / 4 + 255) / 256, 256>>>(x, xh_p, n);
    }
    // 2-3) weights -> half K-major (transposed)
    {
        dim3 blk(32, 8);
        transpose_h_kernel<<<dim3(N_IN / 32, D_MODEL / 32), blk>>>(W_in, w1th_p, D_MODEL, N_IN);
        transpose_h_kernel<<<dim3(D_MODEL / 32, D_INNER / 32), blk>>>(W_out, w2th_p, D_INNER, D_MODEL);
    }
    // 4) xz = x @ W_in   [4096,768] x [768,3072]  (fp16 HMMA, 8 warps)
    {
        dim3 grid(N_IN / 128, MROWS / 128);
        h16_gemm<<<grid, 256, GSTAGES * STAGE_BYTES>>>(xh_p, w1th_p, xz_p, MROWS, N_IN, D_MODEL);
    }
    // 5) causal conv + silu
    {
        int total = MROWS * D_INNER;
        conv_silu_kernel<<<(total + 255) / 256, 256>>>(conv_w, conv_b);
    }
    // 6) x_dbl = x_conv @ W_x
    xdbl_kernel<<<MROWS / 64, 256>>>(W_x);
    // 7) dt = softplus(dt_low @ W_dt + b_dt)
    {
        int total = MROWS * D_INNER;
        dt_kernel<<<(total + 255) / 256, 256>>>(W_dt, b_dt);
    }
    // 8) selective scan + gate (writes half)
    scan_kernel<<<(BB * D_INNER) / 4, 64>>>(A_log, Dvec);
    // 9) out = y_gated @ W_out   [4096,1536] x [1536,768]  (fp16 HMMA, 8 warps)
    {
        dim3 grid(D_MODEL / 128, MROWS / 128);
        h16_gemm<<<grid, 256, GSTAGES * STAGE_BYTES>>>(ygh_p, w2th_p, out, MROWS, D_MODEL, D_INNER);
    }
}

// round 15
// speedup vs baseline: 2.1429x; 1.5226x over previous
#include <cuda_runtime.h>
#include <cuda_fp16.h>
#include <math.h>
#include <stdint.h>

// Problem constants
#define BB 2
#define LL 2048
#define D_MODEL 768
#define D_INNER 1536
#define DT_RANK 16
#define D_STATE 16
#define D_CONV 4
#define MROWS (BB*LL)          // 4096
#define N_IN (2*D_INNER)       // 3072
#define N_DBL (DT_RANK + 2*D_STATE) // 48

// Scratch (static __device__ — no allocation in kernel_launch)
__device__ float  g_xz[(size_t)MROWS * N_IN];        // [4096,3072] fp32
__device__ float  g_xconv[(size_t)MROWS * D_INNER];  // [4096,1536]
__device__ float  g_xdbl[(size_t)MROWS * N_DBL];     // [4096,48]
__device__ float  g_dt[(size_t)MROWS * D_INNER];     // [4096,1536]
__device__ __half g_xh[(size_t)MROWS * D_MODEL];     // x in half
__device__ __half g_w1th[(size_t)N_IN * D_MODEL];    // W_in^T  [3072,768] half
__device__ __half g_w2th[(size_t)D_MODEL * D_INNER]; // W_out^T [768,1536] half
__device__ __half g_ygh[(size_t)MROWS * D_INNER];    // gated y in half

// ---------------------------------------------------------------------------
// FP16 tensor-core GEMM (mma.m16n8k16, fp32 accum), 3-stage cp.async pipeline.
// CTA tile 128x128, 8 warps (4m x 2n), warp tile 32x64, BK=64 halves, SW128.
// __launch_bounds__(256,2): cap regs at 128 -> 2 CTAs/SM (192KB smem fits).
// ---------------------------------------------------------------------------
__device__ __forceinline__ uint32_t smem_u32(const void* p) {
    return (uint32_t)__cvta_generic_to_shared(p);
}
#define CP_ASYNC16(dst, src) \
    asm volatile("cp.async.cg.shared.global [%0], [%1], 16;" :: "r"(dst), "l"(src))
#define CP_COMMIT() asm volatile("cp.async.commit_group;")
#define CP_WAIT2()  asm volatile("cp.async.wait_group 2;")

#define MMA_F16(d, a, b) \
    asm volatile("mma.sync.aligned.m16n8k16.row.col.f32.f16.f16.f32 " \
                 "{%0,%1,%2,%3},{%4,%5,%6,%7},{%8,%9},{%0,%1,%2,%3};" \
                 : "+f"((d)[0]), "+f"((d)[1]), "+f"((d)[2]), "+f"((d)[3]) \
                 : "r"((a)[0]), "r"((a)[1]), "r"((a)[2]), "r"((a)[3]), \
                   "r"((b)[0]), "r"((b)[1]))

// swizzled byte offset within a 128x64-half tile (128B per row)
__device__ __forceinline__ uint32_t sw_off(int r, int col) {
    return ((uint32_t)r << 7) + ((uint32_t)(((col >> 3) ^ (r & 7))) << 4)
         + ((uint32_t)(col & 7) << 1);
}

#define GSTAGES 3
#define TILE_BYTES 16384            // 128 rows * 128 B
#define STAGE_BYTES (2 * TILE_BYTES)

__global__ __launch_bounds__(256, 2) void h16_gemm(
    const __half* __restrict__ A, const __half* __restrict__ Bt,
    float* __restrict__ C, int M, int N, int K)
{
    extern __shared__ __align__(1024) char sm[];

    const int tid  = threadIdx.x;
    const int lane = tid & 31;
    const int warp = tid >> 5;          // 0..7
    const int wm   = warp >> 1;         // 0..3 (32 rows)
    const int wn   = warp & 1;          // 0..1 (64 cols)
    const int bx = blockIdx.x, by = blockIdx.y;
    const int m0 = by * 128, n0 = bx * 128;
    const int KT = K >> 6;              // k-tiles of 64 halves

    // loader: 128x64 halves = 1024 x 16B chunks per matrix; 4 chunks/thread each
#define LOAD_STAGE(s, kt) do { \
        char* smA_ = sm + (s) * STAGE_BYTES; \
        char* smB_ = smA_ + TILE_BYTES; \
        const __half* Agp = A + (size_t)m0 * K + (size_t)(kt) * 64; \
        const __half* Bgp = Bt + (size_t)n0 * K + (size_t)(kt) * 64; \
        _Pragma("unroll") \
        for (int i = 0; i < 4; i++) { \
            int e = tid + (i << 8); \
            int r = e >> 3, c = e & 7; \
            uint32_t off = ((uint32_t)r << 7) + ((uint32_t)((c ^ (r & 7))) << 4); \
            CP_ASYNC16(smem_u32(smA_ + off), Agp + (size_t)r * K + (c << 3)); \
            CP_ASYNC16(smem_u32(smB_ + off), Bgp + (size_t)r * K + (c << 3)); \
        } \
    } while (0)

    LOAD_STAGE(0, 0); CP_COMMIT();
    if (KT > 1) LOAD_STAGE(1, 1);
    CP_COMMIT();

    float acc[2][8][4];
    #pragma unroll
    for (int mt = 0; mt < 2; mt++)
        #pragma unroll
        for (int nt = 0; nt < 8; nt++)
            #pragma unroll
            for (int i = 0; i < 4; i++) acc[mt][nt][i] = 0.f;

    for (int kt = 0; kt < KT; kt++) {
        if (kt + 2 < KT) LOAD_STAGE((kt + 2) % GSTAGES, kt + 2);
        CP_COMMIT();
        CP_WAIT2();              // stage kt ready
        __syncthreads();

        const char* Ab = sm + (kt % GSTAGES) * STAGE_BYTES;
        const char* Bb = Ab + TILE_BYTES;
        const int q2 = 2 * (lane & 3);

        #pragma unroll
        for (int ks = 0; ks < 4; ks++) {
            const int colL = ks * 16 + q2;
            const int colH = colL + 8;
            uint32_t af[2][4];
            #pragma unroll
            for (int mt = 0; mt < 2; mt++) {
                int r1 = wm * 32 + mt * 16 + (lane >> 2);
                af[mt][0] = *(const uint32_t*)(Ab + sw_off(r1,     colL));
                af[mt][1] = *(const uint32_t*)(Ab + sw_off(r1 + 8, colL));
                af[mt][2] = *(const uint32_t*)(Ab + sw_off(r1,     colH));
                af[mt][3] = *(const uint32_t*)(Ab + sw_off(r1 + 8, colH));
            }
            uint32_t bf[8][2];
            #pragma unroll
            for (int nt = 0; nt < 8; nt++) {
                int n1 = wn * 64 + nt * 8 + (lane >> 2);
                bf[nt][0] = *(const uint32_t*)(Bb + sw_off(n1, colL));
                bf[nt][1] = *(const uint32_t*)(Bb + sw_off(n1, colH));
            }
            #pragma unroll
            for (int mt = 0; mt < 2; mt++)
                #pragma unroll
                for (int nt = 0; nt < 8; nt++)
                    MMA_F16(acc[mt][nt], af[mt], bf[nt]);
        }
        __syncthreads();
    }
#undef LOAD_STAGE

    #pragma unroll
    for (int mt = 0; mt < 2; mt++) {
        #pragma unroll
        for (int nt = 0; nt < 8; nt++) {
            int row = m0 + wm * 32 + mt * 16 + (lane >> 2);
            int col = n0 + wn * 64 + nt * 8 + 2 * (lane & 3);
            float2 v0 = make_float2(acc[mt][nt][0], acc[mt][nt][1]);
            float2 v1 = make_float2(acc[mt][nt][2], acc[mt][nt][3]);
            *(float2*)(C + (size_t)row * N + col)       = v0;
            *(float2*)(C + (size_t)(row + 8) * N + col) = v1;
        }
    }
}

// ---------------------------------------------------------------------------
// prep: fused f2h(x) + transpose-to-half of W_in and W_out (ONE launch so the
// ncu capture slot (#4) lands on scan_kernel).
// Block roles by blockIdx.x: [0,3072) f2h, [3072,+2304) W_in^T, rest W_out^T.
// ---------------------------------------------------------------------------
#define NB_F2H  3072                  // (4096*768/4)/256
#define NB_T1   2304                  // (3072/32)*(768/32)
#define NB_T2   1152                  // (768/32)*(1536/32)

__global__ __launch_bounds__(256) void prep_kernel(
    const float* __restrict__ x, const float* __restrict__ W_in,
    const float* __restrict__ W_out)
{
    __shared__ float t[32][33];
    int bid = blockIdx.x;
    if (bid < NB_F2H) {
        __half* out;
        asm("{}" ::: "memory");
        out = (__half*)g_xh;
        int i = (bid * 256 + threadIdx.x) * 4;
        float4 v = *(const float4*)(x + i);
        __half2 h0 = __floats2half2_rn(v.x, v.y);
        __half2 h1 = __floats2half2_rn(v.z, v.w);
        *(uint2*)(out + i) = make_uint2(*(uint32_t*)&h0, *(uint32_t*)&h1);
        return;
    }
    const float* in;
    __half* out;
    int R, C, tidx;
    if (bid < NB_F2H + NB_T1) {
        tidx = bid - NB_F2H;
        in = W_in; out = g_w1th; R = D_MODEL; C = N_IN;     // tiles 96 x 24
    } else {
        tidx = bid - NB_F2H - NB_T1;
        in = W_out; out = g_w2th; R = D_INNER; C = D_MODEL; // tiles 24 x 48
    }
    int tpr = C / 32;                    // tiles per row-of-tiles
    int cb = (tidx % tpr) * 32, rb = (tidx / tpr) * 32;
    int xx = threadIdx.x & 31, yy = threadIdx.x >> 5;   // (32,8)
    #pragma unroll
    for (int i = 0; i < 32; i += 8)
        t[yy + i][xx] = in[(size_t)(rb + yy + i) * C + cb + xx];
    __syncthreads();
    #pragma unroll
    for (int i = 0; i < 32; i += 8)
        out[(size_t)(cb + yy + i) * R + rb + xx] = __float2half(t[xx][yy + i]);
}

// ---------------------------------------------------------------------------
// fusedmid: conv+silu -> smem tile (8 rows x 1536), then xdbl (split-K over
// warp halves) and dt from smem.  Writes g_xconv, g_xdbl, g_dt.
// grid = 512 blocks x 256 threads, ~54KB dynamic smem.
// ---------------------------------------------------------------------------
__global__ __launch_bounds__(256) void fusedmid_kernel(
    const float* __restrict__ conv_w, const float* __restrict__ conv_b,
    const float* __restrict__ Wx,
    const float* __restrict__ Wdt, const float* __restrict__ bdt)
{
    extern __shared__ float smf[];
    float* xc    = smf;                       // 8*1536
    float* part  = smf + 8 * 1536;            // 2*8*48
    float* xdbl8 = part + 2 * 8 * 48;         // 8*48

    const int tid = threadIdx.x;
    const int r0  = blockIdx.x * 8;           // global row base (8 rows/block)

    // Phase 1: conv + silu for 8 rows x 1536 d
    #pragma unroll 4
    for (int i = 0; i < 48; i++) {
        int e = i * 256 + tid;
        int r = e / 1536, d = e - r * 1536;
        int row = r0 + r;
        int l = row & (LL - 1);
        float4 w = *(const float4*)(conv_w + d * 4);
        const float* base = g_xz + (size_t)row * N_IN + d;
        float acc = conv_b[d] + w.w * base[0];
        if (l >= 1) acc += w.z * base[-(ptrdiff_t)N_IN];
        if (l >= 2) acc += w.y * base[-2*(ptrdiff_t)N_IN];
        if (l >= 3) acc += w.x * base[-3*(ptrdiff_t)N_IN];
        float s = acc / (1.f + __expf(-acc));
        xc[r * 1536 + d] = s;
        g_xconv[(size_t)row * D_INNER + d] = s;
    }
    __syncthreads();

    // Phase 2: xdbl[8][48] = xc[8][1536] @ Wx[1536][48], split-K over 2 halves
    {
        const int tx = tid & 15;               // col base (c, c+16, c+32)
        const int ty = tid >> 4;               // 0..15
        const int r  = ty & 7;
        const int hf = ty >> 3;                // 0..1 : k-half
        const int k0 = hf * 768;
        float a0 = 0.f, a1 = 0.f, a2 = 0.f;
        #pragma unroll 4
        for (int k = 0; k < 768; k++) {
            float xv = xc[r * 1536 + k0 + k];
            const float* wrow = Wx + (size_t)(k0 + k) * N_DBL;
            a0 += xv * wrow[tx];
            a1 += xv * wrow[tx + 16];
            a2 += xv * wrow[tx + 32];
        }
        float* pp = part + (hf * 8 + r) * 48;
        pp[tx] = a0; pp[tx + 16] = a1; pp[tx + 32] = a2;
    }
    __syncthreads();
    if ((tid >> 4) < 8) {
        const int tx = tid & 15;
        const int r  = tid >> 4;
        #pragma unroll
        for (int j = 0; j < 3; j++) {
            int c = tx + j * 16;
            float v = part[r * 48 + c] + part[(8 + r) * 48 + c];
            xdbl8[r * 48 + c] = v;
            g_xdbl[(size_t)(r0 + r) * N_DBL + c] = v;
        }
    }
    __syncthreads();

    // Phase 3: dt[8][1536] = softplus(xdbl8[:, :16] @ Wdt + b_dt)
    #pragma unroll 2
    for (int i = 0; i < 48; i++) {
        int e = i * 256 + tid;
        int r = e / 1536, d = e - r * 1536;
        float acc = bdt[d];
        #pragma unroll
        for (int k = 0; k < DT_RANK; k++)
            acc += xdbl8[r * 48 + k] * Wdt[(size_t)k * D_INNER + d];
        g_dt[(size_t)(r0 + r) * D_INNER + d] =
            (acc > 20.f) ? acc : log1pf(__expf(acc));
    }
}

// ---------------------------------------------------------------------------
// Selective scan with deep software pipeline; epilogue writes half for gemm2.
// (unchanged — lands in ncu capture slot #4 this round)
// ---------------------------------------------------------------------------
#define UF 8

__global__ __launch_bounds__(64) void scan_kernel(
    const float* __restrict__ A_log, const float* __restrict__ Dvec)
{
    const int n  = threadIdx.x & 15;
    const int ch = blockIdx.x * 4 + (threadIdx.x >> 4);  // 0..3071
    const int b  = ch / D_INNER;
    const int d  = ch % D_INNER;

    const float A  = -__expf(A_log[d * D_STATE + n]);
    const float Dd = Dvec[d];

    const float* xc  = g_xconv + (size_t)b * LL * D_INNER + d;
    const float* dtp = g_dt    + (size_t)b * LL * D_INNER + d;
    const float* bc  = g_xdbl  + (size_t)b * LL * N_DBL;
    const float* zp  = g_xz    + (size_t)b * LL * N_IN + D_INNER + d;
    __half*      yp  = g_ygh   + (size_t)b * LL * D_INNER + d;

    float h = 0.f;

    float uA[UF], dA_[UF], BA[UF], CA[UF], zA[UF];
    float uB[UF], dB_[UF], BBf[UF], CB[UF], zB[UF];

    auto loadblk = [&](int t0, float* U, float* DT, float* Bv, float* Cv, float* Z) {
        #pragma unroll
        for (int i = 0; i < UF; i++) {
            size_t t = (size_t)(t0 + i);
            U[i]  = __ldg(xc  + t * D_INNER);
            DT[i] = __ldg(dtp + t * D_INNER);
            Bv[i] = __ldg(bc  + t * N_DBL + DT_RANK + n);
            Cv[i] = __ldg(bc  + t * N_DBL + DT_RANK + D_STATE + n);
            Z[i]  = __ldg(zp  + t * N_IN);
        }
    };
    auto compute = [&](int t0, const float* U, const float* DT,
                       const float* Bv, const float* Cv, const float* Z) {
        #pragma unroll
        for (int i = 0; i < UF; i++) {
            float dA = __expf(A * DT[i]);
            h = h * dA + (DT[i] * U[i]) * Bv[i];

            float p = Cv[i] * h;
            p += __shfl_xor_sync(0xffffffffu, p, 8);
            p += __shfl_xor_sync(0xffffffffu, p, 4);
            p += __shfl_xor_sync(0xffffffffu, p, 2);
            p += __shfl_xor_sync(0xffffffffu, p, 1);

            if (n == 0) {
                float zv = Z[i];
                float zs = zv / (1.f + __expf(-zv));
                yp[(size_t)(t0 + i) * D_INNER] = __float2half((p + U[i] * Dd) * zs);
            }
        }
    };

    loadblk(0, uA, dA_, BA, CA, zA);

    for (int t0 = 0; t0 < LL; t0 += 2 * UF) {
        loadblk(t0 + UF, uB, dB_, BBf, CB, zB);
        compute(t0, uA, dA_, BA, CA, zA);
        if (t0 + 2 * UF < LL)
            loadblk(t0 + 2 * UF, uA, dA_, BA, CA, zA);
        compute(t0 + UF, uB, dB_, BBf, CB, zB);
    }
}

// ---------------------------------------------------------------------------
extern "C" void kernel_launch(void* const* d_in, const int* in_sizes, int n_in,
                              void* d_out, int out_size)
{
    const float* x      = (const float*)d_in[0];
    const float* W_in   = (const float*)d_in[1];
    const float* conv_w = (const float*)d_in[2];
    const float* conv_b = (const float*)d_in[3];
    const float* W_x    = (const float*)d_in[4];
    const float* W_dt   = (const float*)d_in[5];
    const float* b_dt   = (const float*)d_in[6];
    const float* A_log  = (const float*)d_in[7];
    const float* Dvec   = (const float*)d_in[8];
    const float* W_out  = (const float*)d_in[9];
    float* out = (float*)d_out;

    float *xz_p;
    __half *xh_p, *w1th_p, *w2th_p, *ygh_p;
    cudaGetSymbolAddress((void**)&xz_p,   g_xz);
    cudaGetSymbolAddress((void**)&xh_p,   g_xh);
    cudaGetSymbolAddress((void**)&w1th_p, g_w1th);
    cudaGetSymbolAddress((void**)&w2th_p, g_w2th);
    cudaGetSymbolAddress((void**)&ygh_p,  g_ygh);

    cudaFuncSetAttribute(h16_gemm, cudaFuncAttributeMaxDynamicSharedMemorySize,
                         GSTAGES * STAGE_BYTES);
    cudaFuncSetAttribute(fusedmid_kernel, cudaFuncAttributeMaxDynamicSharedMemorySize,
                         (8 * 1536 + 2 * 8 * 48 + 8 * 48) * (int)sizeof(float));

    // 1) prep: x->half, W_in^T->half, W_out^T->half   (ONE launch)
    prep_kernel<<<NB_F2H + NB_T1 + NB_T2, 256>>>(x, W_in, W_out);

    // 2) xz = x @ W_in   [4096,768] x [768,3072]  (fp16 HMMA, 2 CTA/SM)
    {
        dim3 grid(N_IN / 128, MROWS / 128);
        h16_gemm<<<grid, 256, GSTAGES * STAGE_BYTES>>>(xh_p, w1th_p, xz_p, MROWS, N_IN, D_MODEL);
    }

    // 3) fused conv+silu / xdbl / dt
    {
        int smem = (8 * 1536 + 2 * 8 * 48 + 8 * 48) * (int)sizeof(float);
        fusedmid_kernel<<<MROWS / 8, 256, smem>>>(conv_w, conv_b, W_x, W_dt, b_dt);
    }

    // 4) selective scan + gate (writes half)   <-- ncu capture slot
    scan_kernel<<<(BB * D_INNER) / 4, 64>>>(A_log, Dvec);

    // 5) out = y_gated @ W_out   [4096,1536] x [1536,768]  (fp16 HMMA)
    {
        dim3 grid(D_MODEL / 128, MROWS / 128);
        h16_gemm<<<grid, 256, GSTAGES * STAGE_BYTES>>>(ygh_p, w2th_p, out, MROWS, D_MODEL, D_INNER);
    }
}

// round 16
// speedup vs baseline: 2.2584x; 1.0539x over previous
#include <cuda_runtime.h>
#include <cuda_fp16.h>
#include <math.h>
#include <stdint.h>

// Problem constants
#define BB 2
#define LL 2048
#define D_MODEL 768
#define D_INNER 1536
#define DT_RANK 16
#define D_STATE 16
#define D_CONV 4
#define MROWS (BB*LL)          // 4096
#define N_IN (2*D_INNER)       // 3072
#define N_DBL (DT_RANK + 2*D_STATE) // 48
#define NCH (BB*D_INNER)       // 3072 channels
#define NCHUNK 8
#define CLEN (LL/NCHUNK)       // 256

// Scratch (static __device__ — no allocation in kernel_launch)
__device__ float  g_xz[(size_t)MROWS * N_IN];        // [4096,3072] fp32
__device__ float  g_xconv[(size_t)MROWS * D_INNER];  // [4096,1536]
__device__ float  g_xdbl[(size_t)MROWS * N_DBL];     // [4096,48]
__device__ float  g_dt[(size_t)MROWS * D_INNER];     // [4096,1536]
__device__ __half g_xh[(size_t)MROWS * D_MODEL];     // x in half
__device__ __half g_w1th[(size_t)N_IN * D_MODEL];    // W_in^T  [3072,768] half
__device__ __half g_w2th[(size_t)D_MODEL * D_INNER]; // W_out^T [768,1536] half
__device__ __half g_ygh[(size_t)MROWS * D_INNER];    // gated y in half
__device__ float  g_H[(size_t)NCHUNK * NCH * D_STATE]; // chunk end-states
__device__ float  g_P[(size_t)NCHUNK * NCH * D_STATE]; // chunk carry factors

// ---------------------------------------------------------------------------
// FP16 tensor-core GEMM (mma.m16n8k16, fp32 accum), 3-stage cp.async pipeline.
// CTA tile 128x128, 8 warps (4m x 2n), warp tile 32x64, BK=64 halves, SW128.
// ---------------------------------------------------------------------------
__device__ __forceinline__ uint32_t smem_u32(const void* p) {
    return (uint32_t)__cvta_generic_to_shared(p);
}
#define CP_ASYNC16(dst, src) \
    asm volatile("cp.async.cg.shared.global [%0], [%1], 16;" :: "r"(dst), "l"(src))
#define CP_COMMIT() asm volatile("cp.async.commit_group;")
#define CP_WAIT2()  asm volatile("cp.async.wait_group 2;")

#define MMA_F16(d, a, b) \
    asm volatile("mma.sync.aligned.m16n8k16.row.col.f32.f16.f16.f32 " \
                 "{%0,%1,%2,%3},{%4,%5,%6,%7},{%8,%9},{%0,%1,%2,%3};" \
                 : "+f"((d)[0]), "+f"((d)[1]), "+f"((d)[2]), "+f"((d)[3]) \
                 : "r"((a)[0]), "r"((a)[1]), "r"((a)[2]), "r"((a)[3]), \
                   "r"((b)[0]), "r"((b)[1]))

__device__ __forceinline__ uint32_t sw_off(int r, int col) {
    return ((uint32_t)r << 7) + ((uint32_t)(((col >> 3) ^ (r & 7))) << 4)
         + ((uint32_t)(col & 7) << 1);
}

#define GSTAGES 3
#define TILE_BYTES 16384            // 128 rows * 128 B
#define STAGE_BYTES (2 * TILE_BYTES)

__global__ __launch_bounds__(256, 2) void h16_gemm(
    const __half* __restrict__ A, const __half* __restrict__ Bt,
    float* __restrict__ C, int M, int N, int K)
{
    extern __shared__ __align__(1024) char sm[];

    const int tid  = threadIdx.x;
    const int lane = tid & 31;
    const int warp = tid >> 5;          // 0..7
    const int wm   = warp >> 1;         // 0..3 (32 rows)
    const int wn   = warp & 1;          // 0..1 (64 cols)
    const int bx = blockIdx.x, by = blockIdx.y;
    const int m0 = by * 128, n0 = bx * 128;
    const int KT = K >> 6;              // k-tiles of 64 halves

#define LOAD_STAGE(s, kt) do { \
        char* smA_ = sm + (s) * STAGE_BYTES; \
        char* smB_ = smA_ + TILE_BYTES; \
        const __half* Agp = A + (size_t)m0 * K + (size_t)(kt) * 64; \
        const __half* Bgp = Bt + (size_t)n0 * K + (size_t)(kt) * 64; \
        _Pragma("unroll") \
        for (int i = 0; i < 4; i++) { \
            int e = tid + (i << 8); \
            int r = e >> 3, c = e & 7; \
            uint32_t off = ((uint32_t)r << 7) + ((uint32_t)((c ^ (r & 7))) << 4); \
            CP_ASYNC16(smem_u32(smA_ + off), Agp + (size_t)r * K + (c << 3)); \
            CP_ASYNC16(smem_u32(smB_ + off), Bgp + (size_t)r * K + (c << 3)); \
        } \
    } while (0)

    LOAD_STAGE(0, 0); CP_COMMIT();
    if (KT > 1) LOAD_STAGE(1, 1);
    CP_COMMIT();

    float acc[2][8][4];
    #pragma unroll
    for (int mt = 0; mt < 2; mt++)
        #pragma unroll
        for (int nt = 0; nt < 8; nt++)
            #pragma unroll
            for (int i = 0; i < 4; i++) acc[mt][nt][i] = 0.f;

    for (int kt = 0; kt < KT; kt++) {
        if (kt + 2 < KT) LOAD_STAGE((kt + 2) % GSTAGES, kt + 2);
        CP_COMMIT();
        CP_WAIT2();
        __syncthreads();

        const char* Ab = sm + (kt % GSTAGES) * STAGE_BYTES;
        const char* Bb = Ab + TILE_BYTES;
        const int q2 = 2 * (lane & 3);

        #pragma unroll
        for (int ks = 0; ks < 4; ks++) {
            const int colL = ks * 16 + q2;
            const int colH = colL + 8;
            uint32_t af[2][4];
            #pragma unroll
            for (int mt = 0; mt < 2; mt++) {
                int r1 = wm * 32 + mt * 16 + (lane >> 2);
                af[mt][0] = *(const uint32_t*)(Ab + sw_off(r1,     colL));
                af[mt][1] = *(const uint32_t*)(Ab + sw_off(r1 + 8, colL));
                af[mt][2] = *(const uint32_t*)(Ab + sw_off(r1,     colH));
                af[mt][3] = *(const uint32_t*)(Ab + sw_off(r1 + 8, colH));
            }
            uint32_t bf[8][2];
            #pragma unroll
            for (int nt = 0; nt < 8; nt++) {
                int n1 = wn * 64 + nt * 8 + (lane >> 2);
                bf[nt][0] = *(const uint32_t*)(Bb + sw_off(n1, colL));
                bf[nt][1] = *(const uint32_t*)(Bb + sw_off(n1, colH));
            }
            #pragma unroll
            for (int mt = 0; mt < 2; mt++)
                #pragma unroll
                for (int nt = 0; nt < 8; nt++)
                    MMA_F16(acc[mt][nt], af[mt], bf[nt]);
        }
        __syncthreads();
    }
#undef LOAD_STAGE

    #pragma unroll
    for (int mt = 0; mt < 2; mt++) {
        #pragma unroll
        for (int nt = 0; nt < 8; nt++) {
            int row = m0 + wm * 32 + mt * 16 + (lane >> 2);
            int col = n0 + wn * 64 + nt * 8 + 2 * (lane & 3);
            float2 v0 = make_float2(acc[mt][nt][0], acc[mt][nt][1]);
            float2 v1 = make_float2(acc[mt][nt][2], acc[mt][nt][3]);
            *(float2*)(C + (size_t)row * N + col)       = v0;
            *(float2*)(C + (size_t)(row + 8) * N + col) = v1;
        }
    }
}

// ---------------------------------------------------------------------------
// prep: fused f2h(x) + transpose-to-half of W_in and W_out (one launch).
// ---------------------------------------------------------------------------
#define NB_F2H  3072
#define NB_T1   2304
#define NB_T2   1152

__global__ __launch_bounds__(256) void prep_kernel(
    const float* __restrict__ x, const float* __restrict__ W_in,
    const float* __restrict__ W_out)
{
    __shared__ float t[32][33];
    int bid = blockIdx.x;
    if (bid < NB_F2H) {
        __half* out = (__half*)g_xh;
        int i = (bid * 256 + threadIdx.x) * 4;
        float4 v = *(const float4*)(x + i);
        __half2 h0 = __floats2half2_rn(v.x, v.y);
        __half2 h1 = __floats2half2_rn(v.z, v.w);
        *(uint2*)(out + i) = make_uint2(*(uint32_t*)&h0, *(uint32_t*)&h1);
        return;
    }
    const float* in;
    __half* out;
    int R, C, tidx;
    if (bid < NB_F2H + NB_T1) {
        tidx = bid - NB_F2H;
        in = W_in; out = g_w1th; R = D_MODEL; C = N_IN;
    } else {
        tidx = bid - NB_F2H - NB_T1;
        in = W_out; out = g_w2th; R = D_INNER; C = D_MODEL;
    }
    int tpr = C / 32;
    int cb = (tidx % tpr) * 32, rb = (tidx / tpr) * 32;
    int xx = threadIdx.x & 31, yy = threadIdx.x >> 5;
    #pragma unroll
    for (int i = 0; i < 32; i += 8)
        t[yy + i][xx] = in[(size_t)(rb + yy + i) * C + cb + xx];
    __syncthreads();
    #pragma unroll
    for (int i = 0; i < 32; i += 8)
        out[(size_t)(cb + yy + i) * R + rb + xx] = __float2half(t[xx][yy + i]);
}

// ---------------------------------------------------------------------------
// fusedmid: conv+silu -> smem tile (8 rows x 1536), then xdbl and dt.
// ---------------------------------------------------------------------------
__global__ __launch_bounds__(256) void fusedmid_kernel(
    const float* __restrict__ conv_w, const float* __restrict__ conv_b,
    const float* __restrict__ Wx,
    const float* __restrict__ Wdt, const float* __restrict__ bdt)
{
    extern __shared__ float smf[];
    float* xc    = smf;                       // 8*1536
    float* part  = smf + 8 * 1536;            // 2*8*48
    float* xdbl8 = part + 2 * 8 * 48;         // 8*48

    const int tid = threadIdx.x;
    const int r0  = blockIdx.x * 8;

    #pragma unroll 4
    for (int i = 0; i < 48; i++) {
        int e = i * 256 + tid;
        int r = e / 1536, d = e - r * 1536;
        int row = r0 + r;
        int l = row & (LL - 1);
        float4 w = *(const float4*)(conv_w + d * 4);
        const float* base = g_xz + (size_t)row * N_IN + d;
        float acc = conv_b[d] + w.w * base[0];
        if (l >= 1) acc += w.z * base[-(ptrdiff_t)N_IN];
        if (l >= 2) acc += w.y * base[-2*(ptrdiff_t)N_IN];
        if (l >= 3) acc += w.x * base[-3*(ptrdiff_t)N_IN];
        float s = acc / (1.f + __expf(-acc));
        xc[r * 1536 + d] = s;
        g_xconv[(size_t)row * D_INNER + d] = s;
    }
    __syncthreads();

    {
        const int tx = tid & 15;
        const int ty = tid >> 4;
        const int r  = ty & 7;
        const int hf = ty >> 3;
        const int k0 = hf * 768;
        float a0 = 0.f, a1 = 0.f, a2 = 0.f;
        #pragma unroll 4
        for (int k = 0; k < 768; k++) {
            float xv = xc[r * 1536 + k0 + k];
            const float* wrow = Wx + (size_t)(k0 + k) * N_DBL;
            a0 += xv * wrow[tx];
            a1 += xv * wrow[tx + 16];
            a2 += xv * wrow[tx + 32];
        }
        float* pp = part + (hf * 8 + r) * 48;
        pp[tx] = a0; pp[tx + 16] = a1; pp[tx + 32] = a2;
    }
    __syncthreads();
    if ((tid >> 4) < 8) {
        const int tx = tid & 15;
        const int r  = tid >> 4;
        #pragma unroll
        for (int j = 0; j < 3; j++) {
            int c = tx + j * 16;
            float v = part[r * 48 + c] + part[(8 + r) * 48 + c];
            xdbl8[r * 48 + c] = v;
            g_xdbl[(size_t)(r0 + r) * N_DBL + c] = v;
        }
    }
    __syncthreads();

    #pragma unroll 2
    for (int i = 0; i < 48; i++) {
        int e = i * 256 + tid;
        int r = e / 1536, d = e - r * 1536;
        float acc = bdt[d];
        #pragma unroll
        for (int k = 0; k < DT_RANK; k++)
            acc += xdbl8[r * 48 + k] * Wdt[(size_t)k * D_INNER + d];
        g_dt[(size_t)(r0 + r) * D_INNER + d] =
            (acc > 20.f) ? acc : log1pf(__expf(acc));
    }
}

// ---------------------------------------------------------------------------
// Chunked selective scan.
// Pass 1: per (chunk,ch,n) scan h with h0=0 over CLEN steps (light body:
//         u, dt, B only) -> H; carry P = exp(A * sum(dt)) (exact collapse).
// Pass 3: per (chunk,ch,n) combine carries (<=7 FMA prologue) then rescan the
//         chunk from h_in with the full body (y, D-residual, z-gate).
// Parallelism: 8x more warps than the monolithic scan (12288 vs 1536).
// ---------------------------------------------------------------------------
#define UF 8

__global__ __launch_bounds__(64) void scan_pass1(const float* __restrict__ A_log)
{
    const int n   = threadIdx.x & 15;
    const int gid = blockIdx.x * 4 + (threadIdx.x >> 4);   // 0..8*3072
    const int c   = gid / NCH;            // chunk
    const int ch  = gid - c * NCH;        // channel 0..3071
    const int b   = ch / D_INNER;
    const int d   = ch - b * D_INNER;
    const int t0g = c * CLEN;             // chunk start (within batch timeline)

    const float A = -__expf(A_log[d * D_STATE + n]);

    const float* xc  = g_xconv + ((size_t)b * LL + t0g) * D_INNER + d;
    const float* dtp = g_dt    + ((size_t)b * LL + t0g) * D_INNER + d;
    const float* bc  = g_xdbl  + ((size_t)b * LL + t0g) * N_DBL;

    float h = 0.f, sdt = 0.f;

    float uA[UF], dA_[UF], BA[UF];
    float uB[UF], dB_[UF], BBf[UF];

    auto loadblk = [&](int t0, float* U, float* DT, float* Bv) {
        #pragma unroll
        for (int i = 0; i < UF; i++) {
            size_t t = (size_t)(t0 + i);
            U[i]  = __ldg(xc  + t * D_INNER);
            DT[i] = __ldg(dtp + t * D_INNER);
            Bv[i] = __ldg(bc  + t * N_DBL + DT_RANK + n);
        }
    };
    auto compute = [&](const float* U, const float* DT, const float* Bv) {
        #pragma unroll
        for (int i = 0; i < UF; i++) {
            float e = __expf(A * DT[i]);
            h = h * e + (DT[i] * U[i]) * Bv[i];
            sdt += DT[i];
        }
    };

    loadblk(0, uA, dA_, BA);
    for (int t0 = 0; t0 < CLEN; t0 += 2 * UF) {
        loadblk(t0 + UF, uB, dB_, BBf);
        compute(uA, dA_, BA);
        if (t0 + 2 * UF < CLEN)
            loadblk(t0 + 2 * UF, uA, dA_, BA);
        compute(uB, dB_, BBf);
    }

    size_t idx = ((size_t)c * NCH + ch) * D_STATE + n;
    g_H[idx] = h;
    g_P[idx] = __expf(A * sdt);
}

__global__ __launch_bounds__(64) void scan_pass3(
    const float* __restrict__ A_log, const float* __restrict__ Dvec)
{
    const int n   = threadIdx.x & 15;
    const int gid = blockIdx.x * 4 + (threadIdx.x >> 4);
    const int c   = gid / NCH;
    const int ch  = gid - c * NCH;
    const int b   = ch / D_INNER;
    const int d   = ch - b * D_INNER;
    const int t0g = c * CLEN;

    const float A  = -__expf(A_log[d * D_STATE + n]);
    const float Dd = Dvec[d];

    const float* xc  = g_xconv + ((size_t)b * LL + t0g) * D_INNER + d;
    const float* dtp = g_dt    + ((size_t)b * LL + t0g) * D_INNER + d;
    const float* bc  = g_xdbl  + ((size_t)b * LL + t0g) * N_DBL;
    const float* zp  = g_xz    + ((size_t)b * LL + t0g) * N_IN + D_INNER + d;
    __half*      yp  = g_ygh   + ((size_t)b * LL + t0g) * D_INNER + d;

    // carry prologue: h_in for this chunk
    float h = 0.f;
    for (int s = 0; s < c; s++) {
        size_t idx = ((size_t)s * NCH + ch) * D_STATE + n;
        h = __ldg(g_H + idx) + __ldg(g_P + idx) * h;
    }

    float uA[UF], dA_[UF], BA[UF], CA[UF], zA[UF];
    float uB[UF], dB_[UF], BBf[UF], CB[UF], zB[UF];

    auto loadblk = [&](int t0, float* U, float* DT, float* Bv, float* Cv, float* Z) {
        #pragma unroll
        for (int i = 0; i < UF; i++) {
            size_t t = (size_t)(t0 + i);
            U[i]  = __ldg(xc  + t * D_INNER);
            DT[i] = __ldg(dtp + t * D_INNER);
            Bv[i] = __ldg(bc  + t * N_DBL + DT_RANK + n);
            Cv[i] = __ldg(bc  + t * N_DBL + DT_RANK + D_STATE + n);
            Z[i]  = __ldg(zp  + t * N_IN);
        }
    };
    auto compute = [&](int t0, const float* U, const float* DT,
                       const float* Bv, const float* Cv, const float* Z) {
        #pragma unroll
        for (int i = 0; i < UF; i++) {
            float e = __expf(A * DT[i]);
            h = h * e + (DT[i] * U[i]) * Bv[i];

            float p = Cv[i] * h;
            p += __shfl_xor_sync(0xffffffffu, p, 8);
            p += __shfl_xor_sync(0xffffffffu, p, 4);
            p += __shfl_xor_sync(0xffffffffu, p, 2);
            p += __shfl_xor_sync(0xffffffffu, p, 1);

            if (n == 0) {
                float zv = Z[i];
                float zs = zv / (1.f + __expf(-zv));
                yp[(size_t)(t0 + i) * D_INNER] = __float2half((p + U[i] * Dd) * zs);
            }
        }
    };

    loadblk(0, uA, dA_, BA, CA, zA);
    for (int t0 = 0; t0 < CLEN; t0 += 2 * UF) {
        loadblk(t0 + UF, uB, dB_, BBf, CB, zB);
        compute(t0, uA, dA_, BA, CA, zA);
        if (t0 + 2 * UF < CLEN)
            loadblk(t0 + 2 * UF, uA, dA_, BA, CA, zA);
        compute(t0 + UF, uB, dB_, BBf, CB, zB);
    }
}

// ---------------------------------------------------------------------------
extern "C" void kernel_launch(void* const* d_in, const int* in_sizes, int n_in,
                              void* d_out, int out_size)
{
    const float* x      = (const float*)d_in[0];
    const float* W_in   = (const float*)d_in[1];
    const float* conv_w = (const float*)d_in[2];
    const float* conv_b = (const float*)d_in[3];
    const float* W_x    = (const float*)d_in[4];
    const float* W_dt   = (const float*)d_in[5];
    const float* b_dt   = (const float*)d_in[6];
    const float* A_log  = (const float*)d_in[7];
    const float* Dvec   = (const float*)d_in[8];
    const float* W_out  = (const float*)d_in[9];
    float* out = (float*)d_out;

    float *xz_p;
    __half *xh_p, *w1th_p, *w2th_p, *ygh_p;
    cudaGetSymbolAddress((void**)&xz_p,   g_xz);
    cudaGetSymbolAddress((void**)&xh_p,   g_xh);
    cudaGetSymbolAddress((void**)&w1th_p, g_w1th);
    cudaGetSymbolAddress((void**)&w2th_p, g_w2th);
    cudaGetSymbolAddress((void**)&ygh_p,  g_ygh);

    cudaFuncSetAttribute(h16_gemm, cudaFuncAttributeMaxDynamicSharedMemorySize,
                         GSTAGES * STAGE_BYTES);
    cudaFuncSetAttribute(fusedmid_kernel, cudaFuncAttributeMaxDynamicSharedMemorySize,
                         (8 * 1536 + 2 * 8 * 48 + 8 * 48) * (int)sizeof(float));

    // 1) prep: x->half, W_in^T->half, W_out^T->half
    prep_kernel<<<NB_F2H + NB_T1 + NB_T2, 256>>>(x, W_in, W_out);

    // 2) xz = x @ W_in   (fp16 HMMA)
    {
        dim3 grid(N_IN / 128, MROWS / 128);
        h16_gemm<<<grid, 256, GSTAGES * STAGE_BYTES>>>(xh_p, w1th_p, xz_p, MROWS, N_IN, D_MODEL);
    }

    // 3) fused conv+silu / xdbl / dt
    {
        int smem = (8 * 1536 + 2 * 8 * 48 + 8 * 48) * (int)sizeof(float);
        fusedmid_kernel<<<MROWS / 8, 256, smem>>>(conv_w, conv_b, W_x, W_dt, b_dt);
    }

    // 4) chunked scan pass 1 (chunk states + carries)   <-- ncu capture slot
    scan_pass1<<<NCHUNK * NCH / 4, 64>>>(A_log);

    // 5) chunked scan pass 3 (carry combine + full rescan + gate)
    scan_pass3<<<NCHUNK * NCH / 4, 64>>>(A_log, Dvec);

    // 6) out = y_gated @ W_out   (fp16 HMMA)
    {
        dim3 grid(D_MODEL / 128, MROWS / 128);
        h16_gemm<<<grid, 256, GSTAGES * STAGE_BYTES>>>(ygh_p, w2th_p, out, MROWS, D_MODEL, D_INNER);
    }
}

// round 17
// speedup vs baseline: 2.6948x; 1.1932x over previous
#include <cuda_runtime.h>
#include <cuda_fp16.h>
#include <math.h>
#include <stdint.h>

// Problem constants
#define BB 2
#define LL 2048
#define D_MODEL 768
#define D_INNER 1536
#define DT_RANK 16
#define D_STATE 16
#define D_CONV 4
#define MROWS (BB*LL)          // 4096
#define N_IN (2*D_INNER)       // 3072
#define N_DBL (DT_RANK + 2*D_STATE) // 48
#define NCH (BB*D_INNER)       // 3072 channels
#define NCHUNK 16
#define CLEN (LL/NCHUNK)       // 128

// Scratch (static __device__ — no allocation in kernel_launch)
__device__ float  g_xz[(size_t)MROWS * N_IN];        // [4096,3072] fp32
__device__ float  g_xconv[(size_t)MROWS * D_INNER];  // [4096,1536]
__device__ float  g_xdbl[(size_t)MROWS * N_DBL];     // [4096,48]
__device__ float  g_dt[(size_t)MROWS * D_INNER];     // [4096,1536]
__device__ __half g_xh[(size_t)MROWS * D_MODEL];     // x in half
__device__ __half g_w1th[(size_t)N_IN * D_MODEL];    // W_in^T  [3072,768] half
__device__ __half g_w2th[(size_t)D_MODEL * D_INNER]; // W_out^T [768,1536] half
__device__ __half g_ygh[(size_t)MROWS * D_INNER];    // gated y in half
__device__ float  g_H[(size_t)NCHUNK * NCH * D_STATE]; // chunk end-states
__device__ float  g_P[(size_t)NCHUNK * NCH * D_STATE]; // chunk carry factors

// ---------------------------------------------------------------------------
// FP16 tensor-core GEMM (mma.m16n8k16, fp32 accum), 3-stage cp.async pipeline.
// CTA tile 128x128, 8 warps (4m x 2n), warp tile 32x64, BK=64 halves, SW128.
// ---------------------------------------------------------------------------
__device__ __forceinline__ uint32_t smem_u32(const void* p) {
    return (uint32_t)__cvta_generic_to_shared(p);
}
#define CP_ASYNC16(dst, src) \
    asm volatile("cp.async.cg.shared.global [%0], [%1], 16;" :: "r"(dst), "l"(src))
#define CP_COMMIT() asm volatile("cp.async.commit_group;")
#define CP_WAIT2()  asm volatile("cp.async.wait_group 2;")

#define MMA_F16(d, a, b) \
    asm volatile("mma.sync.aligned.m16n8k16.row.col.f32.f16.f16.f32 " \
                 "{%0,%1,%2,%3},{%4,%5,%6,%7},{%8,%9},{%0,%1,%2,%3};" \
                 : "+f"((d)[0]), "+f"((d)[1]), "+f"((d)[2]), "+f"((d)[3]) \
                 : "r"((a)[0]), "r"((a)[1]), "r"((a)[2]), "r"((a)[3]), \
                   "r"((b)[0]), "r"((b)[1]))

__device__ __forceinline__ uint32_t sw_off(int r, int col) {
    return ((uint32_t)r << 7) + ((uint32_t)(((col >> 3) ^ (r & 7))) << 4)
         + ((uint32_t)(col & 7) << 1);
}

#define GSTAGES 3
#define TILE_BYTES 16384            // 128 rows * 128 B
#define STAGE_BYTES (2 * TILE_BYTES)

__global__ __launch_bounds__(256, 2) void h16_gemm(
    const __half* __restrict__ A, const __half* __restrict__ Bt,
    float* __restrict__ C, int M, int N, int K)
{
    extern __shared__ __align__(1024) char sm[];

    const int tid  = threadIdx.x;
    const int lane = tid & 31;
    const int warp = tid >> 5;          // 0..7
    const int wm   = warp >> 1;         // 0..3 (32 rows)
    const int wn   = warp & 1;          // 0..1 (64 cols)
    const int bx = blockIdx.x, by = blockIdx.y;
    const int m0 = by * 128, n0 = bx * 128;
    const int KT = K >> 6;              // k-tiles of 64 halves

#define LOAD_STAGE(s, kt) do { \
        char* smA_ = sm + (s) * STAGE_BYTES; \
        char* smB_ = smA_ + TILE_BYTES; \
        const __half* Agp = A + (size_t)m0 * K + (size_t)(kt) * 64; \
        const __half* Bgp = Bt + (size_t)n0 * K + (size_t)(kt) * 64; \
        _Pragma("unroll") \
        for (int i = 0; i < 4; i++) { \
            int e = tid + (i << 8); \
            int r = e >> 3, c = e & 7; \
            uint32_t off = ((uint32_t)r << 7) + ((uint32_t)((c ^ (r & 7))) << 4); \
            CP_ASYNC16(smem_u32(smA_ + off), Agp + (size_t)r * K + (c << 3)); \
            CP_ASYNC16(smem_u32(smB_ + off), Bgp + (size_t)r * K + (c << 3)); \
        } \
    } while (0)

    LOAD_STAGE(0, 0); CP_COMMIT();
    if (KT > 1) LOAD_STAGE(1, 1);
    CP_COMMIT();

    float acc[2][8][4];
    #pragma unroll
    for (int mt = 0; mt < 2; mt++)
        #pragma unroll
        for (int nt = 0; nt < 8; nt++)
            #pragma unroll
            for (int i = 0; i < 4; i++) acc[mt][nt][i] = 0.f;

    for (int kt = 0; kt < KT; kt++) {
        if (kt + 2 < KT) LOAD_STAGE((kt + 2) % GSTAGES, kt + 2);
        CP_COMMIT();
        CP_WAIT2();
        __syncthreads();

        const char* Ab = sm + (kt % GSTAGES) * STAGE_BYTES;
        const char* Bb = Ab + TILE_BYTES;
        const int q2 = 2 * (lane & 3);

        #pragma unroll
        for (int ks = 0; ks < 4; ks++) {
            const int colL = ks * 16 + q2;
            const int colH = colL + 8;
            uint32_t af[2][4];
            #pragma unroll
            for (int mt = 0; mt < 2; mt++) {
                int r1 = wm * 32 + mt * 16 + (lane >> 2);
                af[mt][0] = *(const uint32_t*)(Ab + sw_off(r1,     colL));
                af[mt][1] = *(const uint32_t*)(Ab + sw_off(r1 + 8, colL));
                af[mt][2] = *(const uint32_t*)(Ab + sw_off(r1,     colH));
                af[mt][3] = *(const uint32_t*)(Ab + sw_off(r1 + 8, colH));
            }
            uint32_t bf[8][2];
            #pragma unroll
            for (int nt = 0; nt < 8; nt++) {
                int n1 = wn * 64 + nt * 8 + (lane >> 2);
                bf[nt][0] = *(const uint32_t*)(Bb + sw_off(n1, colL));
                bf[nt][1] = *(const uint32_t*)(Bb + sw_off(n1, colH));
            }
            #pragma unroll
            for (int mt = 0; mt < 2; mt++)
                #pragma unroll
                for (int nt = 0; nt < 8; nt++)
                    MMA_F16(acc[mt][nt], af[mt], bf[nt]);
        }
        __syncthreads();
    }
#undef LOAD_STAGE

    #pragma unroll
    for (int mt = 0; mt < 2; mt++) {
        #pragma unroll
        for (int nt = 0; nt < 8; nt++) {
            int row = m0 + wm * 32 + mt * 16 + (lane >> 2);
            int col = n0 + wn * 64 + nt * 8 + 2 * (lane & 3);
            float2 v0 = make_float2(acc[mt][nt][0], acc[mt][nt][1]);
            float2 v1 = make_float2(acc[mt][nt][2], acc[mt][nt][3]);
            *(float2*)(C + (size_t)row * N + col)       = v0;
            *(float2*)(C + (size_t)(row + 8) * N + col) = v1;
        }
    }
}

// ---------------------------------------------------------------------------
// prep: fused f2h(x) + transpose-to-half of W_in and W_out (one launch).
// ---------------------------------------------------------------------------
#define NB_F2H  3072
#define NB_T1   2304
#define NB_T2   1152

__global__ __launch_bounds__(256) void prep_kernel(
    const float* __restrict__ x, const float* __restrict__ W_in,
    const float* __restrict__ W_out)
{
    __shared__ float t[32][33];
    int bid = blockIdx.x;
    if (bid < NB_F2H) {
        __half* out = (__half*)g_xh;
        int i = (bid * 256 + threadIdx.x) * 4;
        float4 v = *(const float4*)(x + i);
        __half2 h0 = __floats2half2_rn(v.x, v.y);
        __half2 h1 = __floats2half2_rn(v.z, v.w);
        *(uint2*)(out + i) = make_uint2(*(uint32_t*)&h0, *(uint32_t*)&h1);
        return;
    }
    const float* in;
    __half* out;
    int R, C, tidx;
    if (bid < NB_F2H + NB_T1) {
        tidx = bid - NB_F2H;
        in = W_in; out = g_w1th; R = D_MODEL; C = N_IN;
    } else {
        tidx = bid - NB_F2H - NB_T1;
        in = W_out; out = g_w2th; R = D_INNER; C = D_MODEL;
    }
    int tpr = C / 32;
    int cb = (tidx % tpr) * 32, rb = (tidx / tpr) * 32;
    int xx = threadIdx.x & 31, yy = threadIdx.x >> 5;
    #pragma unroll
    for (int i = 0; i < 32; i += 8)
        t[yy + i][xx] = in[(size_t)(rb + yy + i) * C + cb + xx];
    __syncthreads();
    #pragma unroll
    for (int i = 0; i < 32; i += 8)
        out[(size_t)(cb + yy + i) * R + rb + xx] = __float2half(t[xx][yy + i]);
}

// ---------------------------------------------------------------------------
// fusedmid: conv+silu -> smem tile (8 rows x 1536), then xdbl and dt.
// ---------------------------------------------------------------------------
__global__ __launch_bounds__(256) void fusedmid_kernel(
    const float* __restrict__ conv_w, const float* __restrict__ conv_b,
    const float* __restrict__ Wx,
    const float* __restrict__ Wdt, const float* __restrict__ bdt)
{
    extern __shared__ float smf[];
    float* xc    = smf;                       // 8*1536
    float* part  = smf + 8 * 1536;            // 2*8*48
    float* xdbl8 = part + 2 * 8 * 48;         // 8*48

    const int tid = threadIdx.x;
    const int r0  = blockIdx.x * 8;

    #pragma unroll 4
    for (int i = 0; i < 48; i++) {
        int e = i * 256 + tid;
        int r = e / 1536, d = e - r * 1536;
        int row = r0 + r;
        int l = row & (LL - 1);
        float4 w = *(const float4*)(conv_w + d * 4);
        const float* base = g_xz + (size_t)row * N_IN + d;
        float acc = conv_b[d] + w.w * base[0];
        if (l >= 1) acc += w.z * base[-(ptrdiff_t)N_IN];
        if (l >= 2) acc += w.y * base[-2*(ptrdiff_t)N_IN];
        if (l >= 3) acc += w.x * base[-3*(ptrdiff_t)N_IN];
        float s = acc / (1.f + __expf(-acc));
        xc[r * 1536 + d] = s;
        g_xconv[(size_t)row * D_INNER + d] = s;
    }
    __syncthreads();

    {
        const int tx = tid & 15;
        const int ty = tid >> 4;
        const int r  = ty & 7;
        const int hf = ty >> 3;
        const int k0 = hf * 768;
        float a0 = 0.f, a1 = 0.f, a2 = 0.f;
        #pragma unroll 4
        for (int k = 0; k < 768; k++) {
            float xv = xc[r * 1536 + k0 + k];
            const float* wrow = Wx + (size_t)(k0 + k) * N_DBL;
            a0 += xv * wrow[tx];
            a1 += xv * wrow[tx + 16];
            a2 += xv * wrow[tx + 32];
        }
        float* pp = part + (hf * 8 + r) * 48;
        pp[tx] = a0; pp[tx + 16] = a1; pp[tx + 32] = a2;
    }
    __syncthreads();
    if ((tid >> 4) < 8) {
        const int tx = tid & 15;
        const int r  = tid >> 4;
        #pragma unroll
        for (int j = 0; j < 3; j++) {
            int c = tx + j * 16;
            float v = part[r * 48 + c] + part[(8 + r) * 48 + c];
            xdbl8[r * 48 + c] = v;
            g_xdbl[(size_t)(r0 + r) * N_DBL + c] = v;
        }
    }
    __syncthreads();

    #pragma unroll 2
    for (int i = 0; i < 48; i++) {
        int e = i * 256 + tid;
        int r = e / 1536, d = e - r * 1536;
        float acc = bdt[d];
        #pragma unroll
        for (int k = 0; k < DT_RANK; k++)
            acc += xdbl8[r * 48 + k] * Wdt[(size_t)k * D_INNER + d];
        g_dt[(size_t)(r0 + r) * D_INNER + d] =
            (acc > 20.f) ? acc : log1pf(__expf(acc));
    }
}

// ---------------------------------------------------------------------------
// Chunked selective scan (16 chunks of 128 steps).
// Pass 1: per (chunk,ch,n) local scan (h0=0) -> H; carry P = exp(A*sum(dt)).
// Pass 3: combine <=15 carries, rescan chunk with full body (y, D, z-gate).
// UF=4 double-buffered: ~40 buffer regs -> higher residency than UF=8.
// ---------------------------------------------------------------------------
#define UF 4

__global__ __launch_bounds__(64) void scan_pass1(const float* __restrict__ A_log)
{
    const int n   = threadIdx.x & 15;
    const int gid = blockIdx.x * 4 + (threadIdx.x >> 4);
    const int c   = gid / NCH;            // chunk
    const int ch  = gid - c * NCH;        // channel 0..3071
    const int b   = ch / D_INNER;
    const int d   = ch - b * D_INNER;
    const int t0g = c * CLEN;

    const float A = -__expf(A_log[d * D_STATE + n]);

    const float* xc  = g_xconv + ((size_t)b * LL + t0g) * D_INNER + d;
    const float* dtp = g_dt    + ((size_t)b * LL + t0g) * D_INNER + d;
    const float* bc  = g_xdbl  + ((size_t)b * LL + t0g) * N_DBL;

    float h = 0.f, sdt = 0.f;

    float uA[UF], dA_[UF], BA[UF];
    float uB[UF], dB_[UF], BBf[UF];

    auto loadblk = [&](int t0, float* U, float* DT, float* Bv) {
        #pragma unroll
        for (int i = 0; i < UF; i++) {
            size_t t = (size_t)(t0 + i);
            U[i]  = __ldg(xc  + t * D_INNER);
            DT[i] = __ldg(dtp + t * D_INNER);
            Bv[i] = __ldg(bc  + t * N_DBL + DT_RANK + n);
        }
    };
    auto compute = [&](const float* U, const float* DT, const float* Bv) {
        #pragma unroll
        for (int i = 0; i < UF; i++) {
            float e = __expf(A * DT[i]);
            h = h * e + (DT[i] * U[i]) * Bv[i];
            sdt += DT[i];
        }
    };

    loadblk(0, uA, dA_, BA);
    for (int t0 = 0; t0 < CLEN; t0 += 2 * UF) {
        loadblk(t0 + UF, uB, dB_, BBf);
        compute(uA, dA_, BA);
        if (t0 + 2 * UF < CLEN)
            loadblk(t0 + 2 * UF, uA, dA_, BA);
        compute(uB, dB_, BBf);
    }

    size_t idx = ((size_t)c * NCH + ch) * D_STATE + n;
    g_H[idx] = h;
    g_P[idx] = __expf(A * sdt);
}

__global__ __launch_bounds__(64) void scan_pass3(
    const float* __restrict__ A_log, const float* __restrict__ Dvec)
{
    const int n   = threadIdx.x & 15;
    const int gid = blockIdx.x * 4 + (threadIdx.x >> 4);
    const int c   = gid / NCH;
    const int ch  = gid - c * NCH;
    const int b   = ch / D_INNER;
    const int d   = ch - b * D_INNER;
    const int t0g = c * CLEN;

    const float A  = -__expf(A_log[d * D_STATE + n]);
    const float Dd = Dvec[d];

    const float* xc  = g_xconv + ((size_t)b * LL + t0g) * D_INNER + d;
    const float* dtp = g_dt    + ((size_t)b * LL + t0g) * D_INNER + d;
    const float* bc  = g_xdbl  + ((size_t)b * LL + t0g) * N_DBL;
    const float* zp  = g_xz    + ((size_t)b * LL + t0g) * N_IN + D_INNER + d;
    __half*      yp  = g_ygh   + ((size_t)b * LL + t0g) * D_INNER + d;

    // carry prologue: h_in for this chunk
    float h = 0.f;
    #pragma unroll 4
    for (int s = 0; s < c; s++) {
        size_t idx = ((size_t)s * NCH + ch) * D_STATE + n;
        h = __ldg(g_H + idx) + __ldg(g_P + idx) * h;
    }

    const bool lead = (n == 0);

    float uA[UF], dA_[UF], BA[UF], CA[UF], zA[UF];
    float uB[UF], dB_[UF], BBf[UF], CB[UF], zB[UF];

    auto loadblk = [&](int t0, float* U, float* DT, float* Bv, float* Cv, float* Z) {
        #pragma unroll
        for (int i = 0; i < UF; i++) {
            size_t t = (size_t)(t0 + i);
            U[i]  = __ldg(xc  + t * D_INNER);
            DT[i] = __ldg(dtp + t * D_INNER);
            Bv[i] = __ldg(bc  + t * N_DBL + DT_RANK + n);
            Cv[i] = __ldg(bc  + t * N_DBL + DT_RANK + D_STATE + n);
            Z[i]  = lead ? __ldg(zp + t * N_IN) : 0.f;
        }
    };
    auto compute = [&](int t0, const float* U, const float* DT,
                       const float* Bv, const float* Cv, const float* Z) {
        #pragma unroll
        for (int i = 0; i < UF; i++) {
            float e = __expf(A * DT[i]);
            h = h * e + (DT[i] * U[i]) * Bv[i];

            float p = Cv[i] * h;
            p += __shfl_xor_sync(0xffffffffu, p, 8);
            p += __shfl_xor_sync(0xffffffffu, p, 4);
            p += __shfl_xor_sync(0xffffffffu, p, 2);
            p += __shfl_xor_sync(0xffffffffu, p, 1);

            if (lead) {
                float zv = Z[i];
                float zs = zv / (1.f + __expf(-zv));
                yp[(size_t)(t0 + i) * D_INNER] = __float2half((p + U[i] * Dd) * zs);
            }
        }
    };

    loadblk(0, uA, dA_, BA, CA, zA);
    for (int t0 = 0; t0 < CLEN; t0 += 2 * UF) {
        loadblk(t0 + UF, uB, dB_, BBf, CB, zB);
        compute(t0, uA, dA_, BA, CA, zA);
        if (t0 + 2 * UF < CLEN)
            loadblk(t0 + 2 * UF, uA, dA_, BA, CA, zA);
        compute(t0 + UF, uB, dB_, BBf, CB, zB);
    }
}

// ---------------------------------------------------------------------------
extern "C" void kernel_launch(void* const* d_in, const int* in_sizes, int n_in,
                              void* d_out, int out_size)
{
    const float* x      = (const float*)d_in[0];
    const float* W_in   = (const float*)d_in[1];
    const float* conv_w = (const float*)d_in[2];
    const float* conv_b = (const float*)d_in[3];
    const float* W_x    = (const float*)d_in[4];
    const float* W_dt   = (const float*)d_in[5];
    const float* b_dt   = (const float*)d_in[6];
    const float* A_log  = (const float*)d_in[7];
    const float* Dvec   = (const float*)d_in[8];
    const float* W_out  = (const float*)d_in[9];
    float* out = (float*)d_out;

    float *xz_p;
    __half *xh_p, *w1th_p, *w2th_p, *ygh_p;
    cudaGetSymbolAddress((void**)&xz_p,   g_xz);
    cudaGetSymbolAddress((void**)&xh_p,   g_xh);
    cudaGetSymbolAddress((void**)&w1th_p, g_w1th);
    cudaGetSymbolAddress((void**)&w2th_p, g_w2th);
    cudaGetSymbolAddress((void**)&ygh_p,  g_ygh);

    cudaFuncSetAttribute(h16_gemm, cudaFuncAttributeMaxDynamicSharedMemorySize,
                         GSTAGES * STAGE_BYTES);
    cudaFuncSetAttribute(fusedmid_kernel, cudaFuncAttributeMaxDynamicSharedMemorySize,
                         (8 * 1536 + 2 * 8 * 48 + 8 * 48) * (int)sizeof(float));

    // 1) prep: x->half, W_in^T->half, W_out^T->half
    prep_kernel<<<NB_F2H + NB_T1 + NB_T2, 256>>>(x, W_in, W_out);

    // 2) xz = x @ W_in   (fp16 HMMA)
    {
        dim3 grid(N_IN / 128, MROWS / 128);
        h16_gemm<<<grid, 256, GSTAGES * STAGE_BYTES>>>(xh_p, w1th_p, xz_p, MROWS, N_IN, D_MODEL);
    }

    // 3) fused conv+silu / xdbl / dt
    {
        int smem = (8 * 1536 + 2 * 8 * 48 + 8 * 48) * (int)sizeof(float);
        fusedmid_kernel<<<MROWS / 8, 256, smem>>>(conv_w, conv_b, W_x, W_dt, b_dt);
    }

    // 4) chunked scan pass 1   <-- ncu capture slot
    scan_pass1<<<NCHUNK * NCH / 4, 64>>>(A_log);

    // 5) chunked scan pass 3 (carry combine + rescan + gate)
    scan_pass3<<<NCHUNK * NCH / 4, 64>>>(A_log, Dvec);

    // 6) out = y_gated @ W_out   (fp16 HMMA)
    {
        dim3 grid(D_MODEL / 128, MROWS / 128);
        h16_gemm<<<grid, 256, GSTAGES * STAGE_BYTES>>>(ygh_p, w2th_p, out, MROWS, D_MODEL, D_INNER);
    }
}